// round 14
// baseline (speedup 1.0000x reference)
#include <cuda_runtime.h>
#include <cuda_bf16.h>
#include <stdint.h>

#define NN 50000
#define EE 800000
#define TP 12
#define HID 128
#define TEMPD 268
#define TFUT 12
#define KPAD3 288          // conv3 K padded: [u0 128 | u1 128 | ax 12 | pad 20]
#define NCPAD3 384         // wt2 allocation width (GEMM uses 256; tail covers 256..267)

// ---------------- scratch ---------------------------------------------------
__device__ int   g_bad;
__device__ int   g_src[EE];
__device__ int   g_dst[EE];
__device__ float g_deg[NN];
__device__ float g_dinv[NN];
__device__ float g_selfn[NN];
__device__ int   g_rowptr[NN + 1];
__device__ int   g_cursor[NN];
__device__ int   g_csrc[EE];
__device__ float g_cw[EE];
__device__ float g_x[(size_t)NN * TP];          // autoregressive window
__device__ float g_h0[(size_t)NN * HID];
__device__ float g_h1[(size_t)NN * HID];
__device__ float g_prey[NN];
// unified bf16 split operand buffer (zero-init -> pad stays zero)
__device__ __nv_bfloat16 g_a3h[(size_t)NN * KPAD3];
__device__ __nv_bfloat16 g_a3l[(size_t)NN * KPAD3];
__device__ __nv_bfloat16 g_wt1h[HID * HID];
__device__ __nv_bfloat16 g_wt1l[HID * HID];
__device__ __nv_bfloat16 g_wt2h[(size_t)NCPAD3 * KPAD3];   // permuted W2^T
__device__ __nv_bfloat16 g_wt2l[(size_t)NCPAD3 * KPAD3];
__device__ float g_b2p[NCPAD3];
__device__ float g_w3p[NCPAD3];
__device__ float g_wtail[KPAD3 * 12];           // fp32 W2 cols 256..267 in a3-k order

// ---------------- helpers ----------------------------------------------------
__device__ __forceinline__ uint32_t smem_u32(const void* p) {
    uint32_t a;
    asm("{ .reg .u64 t; cvta.to.shared.u64 t, %1; cvt.u32.u64 %0, t; }" : "=r"(a) : "l"(p));
    return a;
}
__device__ __forceinline__ void split4(float4 v, uint2& hi, uint2& lo) {
    __nv_bfloat16 hx = __float2bfloat16_rn(v.x);
    __nv_bfloat16 hy = __float2bfloat16_rn(v.y);
    __nv_bfloat16 hz = __float2bfloat16_rn(v.z);
    __nv_bfloat16 hw = __float2bfloat16_rn(v.w);
    __nv_bfloat16 lx = __float2bfloat16_rn(v.x - __bfloat162float(hx));
    __nv_bfloat16 ly = __float2bfloat16_rn(v.y - __bfloat162float(hy));
    __nv_bfloat16 lz = __float2bfloat16_rn(v.z - __bfloat162float(hz));
    __nv_bfloat16 lw = __float2bfloat16_rn(v.w - __bfloat162float(hw));
    hi.x = (uint32_t)__bfloat16_as_ushort(hx) | ((uint32_t)__bfloat16_as_ushort(hy) << 16);
    hi.y = (uint32_t)__bfloat16_as_ushort(hz) | ((uint32_t)__bfloat16_as_ushort(hw) << 16);
    lo.x = (uint32_t)__bfloat16_as_ushort(lx) | ((uint32_t)__bfloat16_as_ushort(ly) << 16);
    lo.y = (uint32_t)__bfloat16_as_ushort(lz) | ((uint32_t)__bfloat16_as_ushort(lw) << 16);
}
__device__ __forceinline__ void ldm_x4(uint32_t* r, uint32_t addr) {
    asm volatile("ldmatrix.sync.aligned.m8n8.x4.shared.b16 {%0,%1,%2,%3}, [%4];"
                 : "=r"(r[0]), "=r"(r[1]), "=r"(r[2]), "=r"(r[3]) : "r"(addr));
}
__device__ __forceinline__ void mma_bf16(float* c, const uint32_t* a, const uint32_t* b) {
    asm volatile("mma.sync.aligned.m16n8k16.row.col.f32.bf16.bf16.f32 "
                 "{%0,%1,%2,%3}, {%4,%5,%6,%7}, {%8,%9}, {%0,%1,%2,%3};"
                 : "+f"(c[0]), "+f"(c[1]), "+f"(c[2]), "+f"(c[3])
                 : "r"(a[0]), "r"(a[1]), "r"(a[2]), "r"(a[3]), "r"(b[0]), "r"(b[1]));
}
__device__ __forceinline__ void cp16(uint32_t smem, const void* g, int sz) {
    asm volatile("cp.async.cg.shared.global [%0], [%1], 16, %2;"
                 :: "r"(smem), "l"(g), "r"(sz) : "memory");
}
#define CP_COMMIT() asm volatile("cp.async.commit_group;" ::: "memory")
#define CP_WAIT0()  asm volatile("cp.async.wait_group 0;" ::: "memory")

// ---------------- edge-index dtype probe + decode ---------------------------
__global__ void k_probe(const long long* __restrict__ ei) {
    int e = blockIdx.x * blockDim.x + threadIdx.x;
    if (e >= EE) return;
    long long v = ei[e];
    if (v < 0 || v >= NN) atomicOr(&g_bad, 1);
}
__global__ void k_cvt(const void* __restrict__ eiv) {
    int e = blockIdx.x * blockDim.x + threadIdx.x;
    if (e >= EE) return;
    if (g_bad) {
        const int* e32 = (const int*)eiv;
        g_src[e] = e32[e];
        g_dst[e] = e32[EE + e];
    } else {
        const long long* e64 = (const long long*)eiv;
        g_src[e] = (int)e64[e];
        g_dst[e] = (int)e64[EE + e];
    }
}

// ---------------- preprocessing ----------------------------------------------
__global__ void k_init(const float* __restrict__ x) {
    int n = blockIdx.x * blockDim.x + threadIdx.x;
    if (n == 0) g_bad = 0;
    if (n >= NN) return;
    g_deg[n] = 1.0f;
    g_cursor[n] = 0;
    for (int j = 0; j < TP; j++) g_x[n * TP + j] = x[n * TP + j];
}
__global__ void k_deghist(const float* __restrict__ ew) {
    int e = blockIdx.x * blockDim.x + threadIdx.x;
    if (e >= EE) return;
    int d = g_dst[e];
    atomicAdd(&g_deg[d], ew[e]);
    atomicAdd(&g_cursor[d], 1);
}
__global__ void k_scan() {
    __shared__ int sh[1024];
    const int tid = threadIdx.x;
    const int CH = (NN + 1023) / 1024;
    const int start = tid * CH;
    int s = 0;
    for (int i = 0; i < CH; i++) {
        int idx = start + i;
        if (idx < NN) s += g_cursor[idx];
    }
    sh[tid] = s;
    __syncthreads();
    for (int off = 1; off < 1024; off <<= 1) {
        int v = (tid >= off) ? sh[tid - off] : 0;
        __syncthreads();
        sh[tid] += v;
        __syncthreads();
    }
    int run = (tid == 0) ? 0 : sh[tid - 1];
    for (int i = 0; i < CH; i++) {
        int idx = start + i;
        if (idx < NN) {
            int c = g_cursor[idx];
            g_rowptr[idx] = run;
            g_cursor[idx] = run;
            run += c;
            float di = rsqrtf(g_deg[idx]);
            g_dinv[idx] = di;
            g_selfn[idx] = di * di;
        }
    }
    if (tid == 1023) g_rowptr[NN] = sh[1023];
}
__global__ void k_scatter(const float* __restrict__ ew) {
    int e = blockIdx.x * blockDim.x + threadIdx.x;
    if (e >= EE) return;
    int s = g_src[e];
    int d = g_dst[e];
    int pos = atomicAdd(&g_cursor[d], 1);
    g_csrc[pos] = s;
    g_cw[pos] = g_dinv[s] * ew[e] * g_dinv[d];
}

// ---------------- weight prep: transpose + bf16 split + W2 row permutation ---
// a3 k-layout source row: k<256 -> 12+k ; 256<=k<268 -> k-256 ; else pad
__global__ void k_prepw(const float* __restrict__ W1, const float* __restrict__ W2,
                        const float* __restrict__ b2, const float* __restrict__ W3) {
    int idx = blockIdx.x * blockDim.x + threadIdx.x;
    if (idx >= NCPAD3 * KPAD3) return;
    int n = idx / KPAD3, k = idx % KPAD3;
    int r = (k < 256) ? (k + 12) : (k - 256);
    bool valid = (n < TEMPD) && (k < TEMPD);
    float v2 = valid ? W2[(size_t)r * TEMPD + n] : 0.f;
    __nv_bfloat16 h = __float2bfloat16_rn(v2);
    g_wt2h[idx] = h;
    g_wt2l[idx] = __float2bfloat16_rn(v2 - __bfloat162float(h));
    if (n < HID && k < HID) {
        float v1 = W1[(size_t)k * HID + n];
        __nv_bfloat16 h1 = __float2bfloat16_rn(v1);
        g_wt1h[n * HID + k] = h1;
        g_wt1l[n * HID + k] = __float2bfloat16_rn(v1 - __bfloat162float(h1));
    }
    if (n < 12) {   // fp32 tail weights: W2 columns 256..267 in a3-k order
        g_wtail[k * 12 + n] = (k < TEMPD) ? W2[(size_t)r * TEMPD + 256 + n] : 0.f;
    }
    if (k == 0) {
        g_b2p[n] = (n < TEMPD) ? b2[n] : 0.f;
        g_w3p[n] = (n < TEMPD) ? W3[n] : 0.f;
    }
}

// ---------------- HMMA GEMM v4: 128x128 CTA, m32n64 warp tile, cp.async -----
// 2-stage smem pipeline, 2 CTAs/SM.
// MODE 1: g_h1[m][n] = lrelu(D + bias[n])                     (grid.x=1)
// MODE 2: g_prey[m] += sum_n lrelu(D + g_b2p[n]) * g_w3p[n]   (grid.x=2, cols 0..255)
#define SMEM_MMA_BYTES 81920
template <int KCHUNKS, int LDB, int MODE>
__global__ __launch_bounds__(256, 2) void k_mma(const float* __restrict__ bias)
{
    extern __shared__ __align__(16) __nv_bfloat16 smdyn[];
    const int tid = threadIdx.x;
    const int lane = tid & 31;
    const int wid = tid >> 5;
    const int wm = wid & 3;        // 4 warps over M (32 rows each)
    const int wn = wid >> 2;       // 2 warps over N (64 cols each)
    const int m0 = blockIdx.y * 128;
    const int n0 = blockIdx.x * 128;

    const __nv_bfloat16* Bh = (MODE == 1) ? g_wt1h : g_wt2h;
    const __nv_bfloat16* Bl = (MODE == 1) ? g_wt1l : g_wt2l;

    float c[2][8][4];
    #pragma unroll
    for (int i = 0; i < 2; i++)
        #pragma unroll
        for (int j = 0; j < 8; j++)
            #pragma unroll
            for (int q = 0; q < 4; q++) c[i][j][q] = 0.f;

    const int r0s = tid >> 2;
    const int r1s = (tid + 256) >> 2;
    const int c0s = (tid & 3) * 8;
    const int gm0 = m0 + r0s;
    const int gm1 = m0 + r1s;
    const int szA0 = (gm0 < NN) ? 16 : 0;
    const int szA1 = (gm1 < NN) ? 16 : 0;
    const uint32_t smbase = smem_u32(smdyn);

    auto stage_chunk = [&](int kc, int st) {
        const uint32_t sb = smbase + st * 40960;
        const uint32_t off0 = (r0s * 40 + c0s) * 2;
        const uint32_t off1 = (r1s * 40 + c0s) * 2;
        const size_t ga0 = (size_t)gm0 * KPAD3 + kc * 32 + c0s;
        const size_t ga1 = (size_t)gm1 * KPAD3 + kc * 32 + c0s;
        const size_t gb0 = (size_t)(n0 + r0s) * LDB + kc * 32 + c0s;
        const size_t gb1 = (size_t)(n0 + r1s) * LDB + kc * 32 + c0s;
        cp16(sb + off0,         g_a3h + ga0, szA0);
        cp16(sb + off1,         g_a3h + ga1, szA1);
        cp16(sb + 10240 + off0, g_a3l + ga0, szA0);
        cp16(sb + 10240 + off1, g_a3l + ga1, szA1);
        cp16(sb + 20480 + off0, Bh + gb0, 16);
        cp16(sb + 20480 + off1, Bh + gb1, 16);
        cp16(sb + 30720 + off0, Bl + gb0, 16);
        cp16(sb + 30720 + off1, Bl + gb1, 16);
        CP_COMMIT();
    };

    stage_chunk(0, 0);

    #pragma unroll 1
    for (int kc = 0; kc < KCHUNKS; kc++) {
        const int st = kc & 1;
        CP_WAIT0();
        __syncthreads();
        if (kc + 1 < KCHUNKS) stage_chunk(kc + 1, st ^ 1);

        const uint32_t sb = smbase + st * 40960;
        #pragma unroll
        for (int ks = 0; ks < 2; ks++) {
            const int k0 = ks * 16;
            const int arow = wm * 32 + (lane & 15);
            const int acol = k0 + (lane >> 4) * 8;
            uint32_t ah[2][4], al[2][4];
            ldm_x4(ah[0], sb + (arow * 40 + acol) * 2);
            ldm_x4(ah[1], sb + ((arow + 16) * 40 + acol) * 2);
            ldm_x4(al[0], sb + 10240 + (arow * 40 + acol) * 2);
            ldm_x4(al[1], sb + 10240 + ((arow + 16) * 40 + acol) * 2);

            const int brr = (lane & 7) + ((lane >> 4) << 3);
            const int bcc = k0 + ((lane >> 3) & 1) * 8;
            #pragma unroll
            for (int np = 0; np < 4; np++) {
                const int nb = wn * 64 + np * 16 + brr;
                uint32_t rh[4], rl[4];
                ldm_x4(rh, sb + 20480 + (nb * 40 + bcc) * 2);
                ldm_x4(rl, sb + 30720 + (nb * 40 + bcc) * 2);
                uint32_t bh0[2] = {rh[0], rh[1]}, bh1[2] = {rh[2], rh[3]};
                uint32_t bl0[2] = {rl[0], rl[1]}, bl1[2] = {rl[2], rl[3]};
                #pragma unroll
                for (int mt = 0; mt < 2; mt++) {
                    mma_bf16(c[mt][np * 2],     ah[mt], bh0);
                    mma_bf16(c[mt][np * 2],     ah[mt], bl0);
                    mma_bf16(c[mt][np * 2],     al[mt], bh0);
                    mma_bf16(c[mt][np * 2 + 1], ah[mt], bh1);
                    mma_bf16(c[mt][np * 2 + 1], ah[mt], bl1);
                    mma_bf16(c[mt][np * 2 + 1], al[mt], bh1);
                }
            }
        }
        __syncthreads();
    }

    // ---- epilogue (R10-validated m32n64 mapping) ----
    const int rbase = m0 + wm * 32 + (lane >> 2);
    const int cbase = wn * 64 + 2 * (lane & 3);
    if (MODE == 1) {
        #pragma unroll
        for (int mt = 0; mt < 2; mt++) {
            const int r0 = rbase + mt * 16;
            const int r1 = r0 + 8;
            #pragma unroll
            for (int nt = 0; nt < 8; nt++) {
                const int nc = n0 + cbase + nt * 8;
                float b0v = bias[nc], b1v = bias[nc + 1];
                float v0 = c[mt][nt][0] + b0v, v1 = c[mt][nt][1] + b1v;
                float v2 = c[mt][nt][2] + b0v, v3 = c[mt][nt][3] + b1v;
                v0 = (v0 > 0.f) ? v0 : 0.01f * v0;
                v1 = (v1 > 0.f) ? v1 : 0.01f * v1;
                v2 = (v2 > 0.f) ? v2 : 0.01f * v2;
                v3 = (v3 > 0.f) ? v3 : 0.01f * v3;
                if (r0 < NN) *(float2*)&g_h1[(size_t)r0 * HID + nc] = make_float2(v0, v1);
                if (r1 < NN) *(float2*)&g_h1[(size_t)r1 * HID + nc] = make_float2(v2, v3);
            }
        }
    } else {
        #pragma unroll
        for (int mt = 0; mt < 2; mt++) {
            float p0 = 0.f, p1 = 0.f;
            #pragma unroll
            for (int nt = 0; nt < 8; nt++) {
                const int nc = n0 + cbase + nt * 8;
                float b0v = g_b2p[nc], b1v = g_b2p[nc + 1];
                float w0v = g_w3p[nc], w1v = g_w3p[nc + 1];
                float v0 = c[mt][nt][0] + b0v, v1 = c[mt][nt][1] + b1v;
                float v2 = c[mt][nt][2] + b0v, v3 = c[mt][nt][3] + b1v;
                v0 = (v0 > 0.f) ? v0 : 0.01f * v0;
                v1 = (v1 > 0.f) ? v1 : 0.01f * v1;
                v2 = (v2 > 0.f) ? v2 : 0.01f * v2;
                v3 = (v3 > 0.f) ? v3 : 0.01f * v3;
                p0 += v0 * w0v + v1 * w1v;
                p1 += v2 * w0v + v3 * w1v;
            }
            p0 += __shfl_xor_sync(0xffffffffu, p0, 1);
            p0 += __shfl_xor_sync(0xffffffffu, p0, 2);
            p1 += __shfl_xor_sync(0xffffffffu, p1, 1);
            p1 += __shfl_xor_sync(0xffffffffu, p1, 2);
            if ((lane & 3) == 0) {
                const int r0 = rbase + mt * 16;
                const int r1 = r0 + 8;
                if (r0 < NN) atomicAdd(&g_prey[r0], p0);
                if (r1 < NN) atomicAdd(&g_prey[r1], p1);
            }
        }
    }
}

// ---------------- conv3 tail: outputs 256..267 (SIMT, exact fp32) -----------
// g_prey[n] += sum_{j<12} lrelu( u_n . wtail[:,j] + b2p[256+j] ) * w3p[256+j]
__global__ __launch_bounds__(256) void k_tail()
{
    const int n = blockIdx.x * blockDim.x + threadIdx.x;
    if (n >= NN) return;
    float acc[12];
    #pragma unroll
    for (int j = 0; j < 12; j++) acc[j] = g_b2p[256 + j];
    const __nv_bfloat16* rh = &g_a3h[(size_t)n * KPAD3];
    const __nv_bfloat16* rl = &g_a3l[(size_t)n * KPAD3];
    #pragma unroll 2
    for (int k = 0; k < TEMPD; k += 4) {
        uint2 hh = *(const uint2*)(rh + k);
        uint2 ll = *(const uint2*)(rl + k);
        float u0 = __bfloat162float(__ushort_as_bfloat16((unsigned short)(hh.x & 0xffff))) +
                   __bfloat162float(__ushort_as_bfloat16((unsigned short)(ll.x & 0xffff)));
        float u1 = __bfloat162float(__ushort_as_bfloat16((unsigned short)(hh.x >> 16))) +
                   __bfloat162float(__ushort_as_bfloat16((unsigned short)(ll.x >> 16)));
        float u2 = __bfloat162float(__ushort_as_bfloat16((unsigned short)(hh.y & 0xffff))) +
                   __bfloat162float(__ushort_as_bfloat16((unsigned short)(ll.y & 0xffff)));
        float u3 = __bfloat162float(__ushort_as_bfloat16((unsigned short)(hh.y >> 16))) +
                   __bfloat162float(__ushort_as_bfloat16((unsigned short)(ll.y >> 16)));
        const float* w0 = &g_wtail[(k + 0) * 12];
        const float* w1 = &g_wtail[(k + 1) * 12];
        const float* w2 = &g_wtail[(k + 2) * 12];
        const float* w3 = &g_wtail[(k + 3) * 12];
        #pragma unroll
        for (int j = 0; j < 12; j++)
            acc[j] += u0 * w0[j] + u1 * w1[j] + u2 * w2[j] + u3 * w3[j];
    }
    float s = 0.f;
    #pragma unroll
    for (int j = 0; j < 12; j++) {
        float v = acc[j];
        v = (v > 0.f) ? v : 0.01f * v;
        s += v * g_w3p[256 + j];
    }
    atomicAdd(&g_prey[n], s);
}

// ---------------- fused: aggregate x (12-wide) + conv1 in-warp ---------------
__global__ __launch_bounds__(256) void k_aggx1(const float* __restrict__ W0,
                                               const float* __restrict__ b0)
{
    const int lane = threadIdx.x & 31;
    const int node = (blockIdx.x * blockDim.x + threadIdx.x) >> 5;
    if (node >= NN) return;
    const bool act = lane < 3;
    float4 a = make_float4(0.f, 0.f, 0.f, 0.f);
    if (act) {
        a = *(const float4*)&g_x[(size_t)node * TP + lane * 4];
        float sn = g_selfn[node];
        a.x *= sn; a.y *= sn; a.z *= sn; a.w *= sn;
    }
    const int beg = g_rowptr[node];
    const int end = g_rowptr[node + 1];
    for (int base = beg; base < end; base += 32) {
        int idx = base + lane;
        bool ok = idx < end;
        int   s = ok ? g_csrc[idx] : 0;
        float w = ok ? g_cw[idx]   : 0.f;
        int cnt = min(32, end - base);
        int i = 0;
        for (; i + 4 <= cnt; i += 4) {
            int s0 = __shfl_sync(0xffffffffu, s, i);
            int s1 = __shfl_sync(0xffffffffu, s, i + 1);
            int s2 = __shfl_sync(0xffffffffu, s, i + 2);
            int s3 = __shfl_sync(0xffffffffu, s, i + 3);
            float w0 = __shfl_sync(0xffffffffu, w, i);
            float w1 = __shfl_sync(0xffffffffu, w, i + 1);
            float w2 = __shfl_sync(0xffffffffu, w, i + 2);
            float w3 = __shfl_sync(0xffffffffu, w, i + 3);
            if (act) {
                float4 p0 = *(const float4*)&g_x[(size_t)s0 * TP + lane * 4];
                float4 p1 = *(const float4*)&g_x[(size_t)s1 * TP + lane * 4];
                float4 p2 = *(const float4*)&g_x[(size_t)s2 * TP + lane * 4];
                float4 p3 = *(const float4*)&g_x[(size_t)s3 * TP + lane * 4];
                a.x += p0.x * w0 + p1.x * w1 + p2.x * w2 + p3.x * w3;
                a.y += p0.y * w0 + p1.y * w1 + p2.y * w2 + p3.y * w3;
                a.z += p0.z * w0 + p1.z * w1 + p2.z * w2 + p3.z * w3;
                a.w += p0.w * w0 + p1.w * w1 + p2.w * w2 + p3.w * w3;
            }
        }
        for (; i < cnt; i++) {
            int   ss = __shfl_sync(0xffffffffu, s, i);
            float wwv = __shfl_sync(0xffffffffu, w, i);
            if (act) {
                float4 p = *(const float4*)&g_x[(size_t)ss * TP + lane * 4];
                a.x += p.x * wwv; a.y += p.y * wwv;
                a.z += p.z * wwv; a.w += p.w * wwv;
            }
        }
    }
    if (act) {
        uint2 hi, lo;
        split4(a, hi, lo);
        *(uint2*)&g_a3h[(size_t)node * KPAD3 + 256 + lane * 4] = hi;
        *(uint2*)&g_a3l[(size_t)node * KPAD3 + 256 + lane * 4] = lo;
    }
    float axv[TP];
    #pragma unroll
    for (int k2 = 0; k2 < 3; k2++) {
        axv[k2 * 4 + 0] = __shfl_sync(0xffffffffu, a.x, k2);
        axv[k2 * 4 + 1] = __shfl_sync(0xffffffffu, a.y, k2);
        axv[k2 * 4 + 2] = __shfl_sync(0xffffffffu, a.z, k2);
        axv[k2 * 4 + 3] = __shfl_sync(0xffffffffu, a.w, k2);
    }
    float4 h = *(const float4*)&b0[lane * 4];
    #pragma unroll
    for (int k = 0; k < TP; k++) {
        float4 wv = *(const float4*)&W0[k * HID + lane * 4];
        h.x += axv[k] * wv.x; h.y += axv[k] * wv.y;
        h.z += axv[k] * wv.z; h.w += axv[k] * wv.w;
    }
    h.x = (h.x > 0.f) ? h.x : 0.01f * h.x;
    h.y = (h.y > 0.f) ? h.y : 0.01f * h.y;
    h.z = (h.z > 0.f) ? h.z : 0.01f * h.z;
    h.w = (h.w > 0.f) ? h.w : 0.01f * h.w;
    *(float4*)&g_h0[(size_t)node * HID + lane * 4] = h;
}

// ---------------- aggregation of h buffers (128-wide) -----------------------
template <int SRCSEL, int DOFF, int ZEROPREY>
__global__ __launch_bounds__(256) void k_aggu()
{
    const int lane = threadIdx.x & 31;
    const int node = (blockIdx.x * blockDim.x + threadIdx.x) >> 5;
    if (node >= NN) return;
    const float4* src4 = (const float4*)(SRCSEL == 0 ? g_h0 : g_h1);
    float4 acc = src4[(size_t)node * 32 + lane];
    float sn = g_selfn[node];
    acc.x *= sn; acc.y *= sn; acc.z *= sn; acc.w *= sn;
    const int beg = g_rowptr[node];
    const int end = g_rowptr[node + 1];
    for (int base = beg; base < end; base += 32) {
        int idx = base + lane;
        bool ok = idx < end;
        int   s = ok ? g_csrc[idx] : 0;
        float w = ok ? g_cw[idx]   : 0.f;
        int cnt = min(32, end - base);
        int i = 0;
        for (; i + 4 <= cnt; i += 4) {
            int s0 = __shfl_sync(0xffffffffu, s, i);
            int s1 = __shfl_sync(0xffffffffu, s, i + 1);
            int s2 = __shfl_sync(0xffffffffu, s, i + 2);
            int s3 = __shfl_sync(0xffffffffu, s, i + 3);
            float w0 = __shfl_sync(0xffffffffu, w, i);
            float w1 = __shfl_sync(0xffffffffu, w, i + 1);
            float w2 = __shfl_sync(0xffffffffu, w, i + 2);
            float w3 = __shfl_sync(0xffffffffu, w, i + 3);
            float4 p0 = src4[(size_t)s0 * 32 + lane];
            float4 p1 = src4[(size_t)s1 * 32 + lane];
            float4 p2 = src4[(size_t)s2 * 32 + lane];
            float4 p3 = src4[(size_t)s3 * 32 + lane];
            acc.x += p0.x * w0 + p1.x * w1 + p2.x * w2 + p3.x * w3;
            acc.y += p0.y * w0 + p1.y * w1 + p2.y * w2 + p3.y * w3;
            acc.z += p0.z * w0 + p1.z * w1 + p2.z * w2 + p3.z * w3;
            acc.w += p0.w * w0 + p1.w * w1 + p2.w * w2 + p3.w * w3;
        }
        for (; i < cnt; i++) {
            int   ss = __shfl_sync(0xffffffffu, s, i);
            float wwv = __shfl_sync(0xffffffffu, w, i);
            float4 p = src4[(size_t)ss * 32 + lane];
            acc.x += p.x * wwv; acc.y += p.y * wwv;
            acc.z += p.z * wwv; acc.w += p.w * wwv;
        }
    }
    uint2 hi, lo;
    split4(acc, hi, lo);
    *(uint2*)&g_a3h[(size_t)node * KPAD3 + DOFF + lane * 4] = hi;
    *(uint2*)&g_a3l[(size_t)node * KPAD3 + DOFF + lane * 4] = lo;
    if (ZEROPREY && lane == 0) g_prey[node] = 0.f;
}

// ---------------- scalar aggregation + output + autoregressive shift --------
__global__ void k_agg1(const float* __restrict__ b3, float* __restrict__ out, int tstep) {
    int n = blockIdx.x * blockDim.x + threadIdx.x;
    if (n >= NN) return;
    float acc = g_selfn[n] * g_prey[n];
    int beg = g_rowptr[n], end = g_rowptr[n + 1];
    #pragma unroll 4
    for (int i = beg; i < end; i++)
        acc += g_prey[g_csrc[i]] * g_cw[i];
    float yp = acc + b3[0];
    out[(size_t)n * TFUT + tstep] = yp;
    size_t base = (size_t)n * TP;
    float xv[TP - 1];
    #pragma unroll
    for (int j = 0; j < TP - 1; j++) xv[j] = g_x[base + j + 1];
    #pragma unroll
    for (int j = 0; j < TP - 1; j++) g_x[base + j] = xv[j];
    g_x[base + TP - 1] = yp;
}

// ---------------- launch ------------------------------------------------------
extern "C" void kernel_launch(void* const* d_in, const int* in_sizes, int n_in,
                              void* d_out, int out_size)
{
    const float* x  = (const float*)d_in[0];
    const void*  ei = d_in[1];
    const float* ew = (const float*)d_in[2];
    const float* W0 = (const float*)d_in[3];
    const float* b0 = (const float*)d_in[4];
    const float* W1 = (const float*)d_in[5];
    const float* b1 = (const float*)d_in[6];
    const float* W2 = (const float*)d_in[7];
    const float* b2 = (const float*)d_in[8];
    const float* W3 = (const float*)d_in[9];
    const float* b3 = (const float*)d_in[10];
    float* out = (float*)d_out;

    cudaFuncSetAttribute(k_mma<KPAD3 / 32, KPAD3, 2>,
                         cudaFuncAttributeMaxDynamicSharedMemorySize, SMEM_MMA_BYTES);
    cudaFuncSetAttribute(k_mma<HID / 32, HID, 1>,
                         cudaFuncAttributeMaxDynamicSharedMemorySize, SMEM_MMA_BYTES);

    const int NB = (NN + 255) / 256;
    const int EB = (EE + 255) / 256;
    const int MT = (NN + 127) / 128;             // 391 row tiles
    const int AGGB = (NN * 32 + 255) / 256;
    const int PWB = (NCPAD3 * KPAD3 + 255) / 256;

    k_init<<<NB, 256>>>(x);
    k_probe<<<EB, 256>>>((const long long*)ei);
    k_cvt<<<EB, 256>>>(ei);
    k_prepw<<<PWB, 256>>>(W1, W2, b2, W3);
    k_deghist<<<EB, 256>>>(ew);
    k_scan<<<1, 1024>>>();
    k_scatter<<<EB, 256>>>(ew);

    for (int t = 0; t < TFUT; t++) {
        k_aggx1<<<AGGB, 256>>>(W0, b0);                              // ax->a3[256:268]; h0
        k_aggu<0, 0, 0><<<AGGB, 256>>>();                            // u0 -> a3[0:128]
        k_mma<HID / 32, HID, 1><<<dim3(1, MT), 256, SMEM_MMA_BYTES>>>(b1);        // h1
        k_aggu<1, HID, 1><<<AGGB, 256>>>();                          // u1 -> a3[128:256]; prey=0
        k_mma<KPAD3 / 32, KPAD3, 2><<<dim3(2, MT), 256, SMEM_MMA_BYTES>>>(nullptr); // cols 0..255
        k_tail<<<NB, 256>>>();                                       // cols 256..267 (exact)
        k_agg1<<<NB, 256>>>(b3, out, t);                             // yp, out, shift
    }
}

// round 15
// speedup vs baseline: 1.1964x; 1.1964x over previous
#include <cuda_runtime.h>
#include <cuda_bf16.h>
#include <stdint.h>

#define NN 50000
#define EE 800000
#define TP 12
#define HID 128
#define TEMPD 268
#define TFUT 12
#define KPAD3 288          // conv3 K padded: [u0 128 | u1 128 | ax 12 | pad 20]
#define NCPAD3 384         // wt2 allocation width (tiles: 128+128+64 -> 320 used)

// ---------------- scratch ---------------------------------------------------
__device__ int   g_bad;
__device__ int   g_src[EE];
__device__ int   g_dst[EE];
__device__ float g_deg[NN];
__device__ float g_dinv[NN];
__device__ float g_selfn[NN];
__device__ int   g_rowptr[NN + 1];
__device__ int   g_cursor[NN];
__device__ int   g_csrc[EE];
__device__ float g_cw[EE];
__device__ float g_x[(size_t)NN * TP];          // autoregressive window
__device__ float g_h0[(size_t)NN * HID];
__device__ float g_h1[(size_t)NN * HID];
__device__ float g_prey[NN];
// unified bf16 split operand buffer (zero-init -> pad stays zero)
__device__ __nv_bfloat16 g_a3h[(size_t)NN * KPAD3];
__device__ __nv_bfloat16 g_a3l[(size_t)NN * KPAD3];
__device__ __nv_bfloat16 g_wt1h[HID * HID];
__device__ __nv_bfloat16 g_wt1l[HID * HID];
__device__ __nv_bfloat16 g_wt2h[(size_t)NCPAD3 * KPAD3];   // permuted W2^T
__device__ __nv_bfloat16 g_wt2l[(size_t)NCPAD3 * KPAD3];
__device__ float g_b2p[NCPAD3];
__device__ float g_w3p[NCPAD3];

// ---------------- helpers ----------------------------------------------------
__device__ __forceinline__ uint32_t smem_u32(const void* p) {
    uint32_t a;
    asm("{ .reg .u64 t; cvta.to.shared.u64 t, %1; cvt.u32.u64 %0, t; }" : "=r"(a) : "l"(p));
    return a;
}
__device__ __forceinline__ void split4(float4 v, uint2& hi, uint2& lo) {
    __nv_bfloat16 hx = __float2bfloat16_rn(v.x);
    __nv_bfloat16 hy = __float2bfloat16_rn(v.y);
    __nv_bfloat16 hz = __float2bfloat16_rn(v.z);
    __nv_bfloat16 hw = __float2bfloat16_rn(v.w);
    __nv_bfloat16 lx = __float2bfloat16_rn(v.x - __bfloat162float(hx));
    __nv_bfloat16 ly = __float2bfloat16_rn(v.y - __bfloat162float(hy));
    __nv_bfloat16 lz = __float2bfloat16_rn(v.z - __bfloat162float(hz));
    __nv_bfloat16 lw = __float2bfloat16_rn(v.w - __bfloat162float(hw));
    hi.x = (uint32_t)__bfloat16_as_ushort(hx) | ((uint32_t)__bfloat16_as_ushort(hy) << 16);
    hi.y = (uint32_t)__bfloat16_as_ushort(hz) | ((uint32_t)__bfloat16_as_ushort(hw) << 16);
    lo.x = (uint32_t)__bfloat16_as_ushort(lx) | ((uint32_t)__bfloat16_as_ushort(ly) << 16);
    lo.y = (uint32_t)__bfloat16_as_ushort(lz) | ((uint32_t)__bfloat16_as_ushort(lw) << 16);
}
__device__ __forceinline__ void ldm_x4(uint32_t* r, uint32_t addr) {
    asm volatile("ldmatrix.sync.aligned.m8n8.x4.shared.b16 {%0,%1,%2,%3}, [%4];"
                 : "=r"(r[0]), "=r"(r[1]), "=r"(r[2]), "=r"(r[3]) : "r"(addr));
}
__device__ __forceinline__ void mma_bf16(float* c, const uint32_t* a, const uint32_t* b) {
    asm volatile("mma.sync.aligned.m16n8k16.row.col.f32.bf16.bf16.f32 "
                 "{%0,%1,%2,%3}, {%4,%5,%6,%7}, {%8,%9}, {%0,%1,%2,%3};"
                 : "+f"(c[0]), "+f"(c[1]), "+f"(c[2]), "+f"(c[3])
                 : "r"(a[0]), "r"(a[1]), "r"(a[2]), "r"(a[3]), "r"(b[0]), "r"(b[1]));
}
__device__ __forceinline__ void cp16(uint32_t smem, const void* g, int sz) {
    asm volatile("cp.async.cg.shared.global [%0], [%1], 16, %2;"
                 :: "r"(smem), "l"(g), "r"(sz) : "memory");
}
#define CP_COMMIT() asm volatile("cp.async.commit_group;" ::: "memory")
#define CP_WAIT0()  asm volatile("cp.async.wait_group 0;" ::: "memory")

// ---------------- edge-index dtype probe + decode ---------------------------
__global__ void k_probe(const long long* __restrict__ ei) {
    int e = blockIdx.x * blockDim.x + threadIdx.x;
    if (e >= EE) return;
    long long v = ei[e];
    if (v < 0 || v >= NN) atomicOr(&g_bad, 1);
}
__global__ void k_cvt(const void* __restrict__ eiv) {
    int e = blockIdx.x * blockDim.x + threadIdx.x;
    if (e >= EE) return;
    if (g_bad) {
        const int* e32 = (const int*)eiv;
        g_src[e] = e32[e];
        g_dst[e] = e32[EE + e];
    } else {
        const long long* e64 = (const long long*)eiv;
        g_src[e] = (int)e64[e];
        g_dst[e] = (int)e64[EE + e];
    }
}

// ---------------- preprocessing ----------------------------------------------
__global__ void k_init(const float* __restrict__ x) {
    int n = blockIdx.x * blockDim.x + threadIdx.x;
    if (n == 0) g_bad = 0;
    if (n >= NN) return;
    g_deg[n] = 1.0f;
    g_cursor[n] = 0;
    for (int j = 0; j < TP; j++) g_x[n * TP + j] = x[n * TP + j];
}
__global__ void k_deghist(const float* __restrict__ ew) {
    int e = blockIdx.x * blockDim.x + threadIdx.x;
    if (e >= EE) return;
    int d = g_dst[e];
    atomicAdd(&g_deg[d], ew[e]);
    atomicAdd(&g_cursor[d], 1);
}
__global__ void k_scan() {
    __shared__ int sh[1024];
    const int tid = threadIdx.x;
    const int CH = (NN + 1023) / 1024;
    const int start = tid * CH;
    int s = 0;
    for (int i = 0; i < CH; i++) {
        int idx = start + i;
        if (idx < NN) s += g_cursor[idx];
    }
    sh[tid] = s;
    __syncthreads();
    for (int off = 1; off < 1024; off <<= 1) {
        int v = (tid >= off) ? sh[tid - off] : 0;
        __syncthreads();
        sh[tid] += v;
        __syncthreads();
    }
    int run = (tid == 0) ? 0 : sh[tid - 1];
    for (int i = 0; i < CH; i++) {
        int idx = start + i;
        if (idx < NN) {
            int c = g_cursor[idx];
            g_rowptr[idx] = run;
            g_cursor[idx] = run;
            run += c;
            float di = rsqrtf(g_deg[idx]);
            g_dinv[idx] = di;
            g_selfn[idx] = di * di;
        }
    }
    if (tid == 1023) g_rowptr[NN] = sh[1023];
}
__global__ void k_scatter(const float* __restrict__ ew) {
    int e = blockIdx.x * blockDim.x + threadIdx.x;
    if (e >= EE) return;
    int s = g_src[e];
    int d = g_dst[e];
    int pos = atomicAdd(&g_cursor[d], 1);
    g_csrc[pos] = s;
    g_cw[pos] = g_dinv[s] * ew[e] * g_dinv[d];
}

// ---------------- weight prep: transpose + bf16 split + W2 row permutation ---
// a3 k-layout source row: k<256 -> 12+k ; 256<=k<268 -> k-256 ; else pad
__global__ void k_prepw(const float* __restrict__ W1, const float* __restrict__ W2,
                        const float* __restrict__ b2, const float* __restrict__ W3) {
    int idx = blockIdx.x * blockDim.x + threadIdx.x;
    if (idx >= NCPAD3 * KPAD3) return;
    int n = idx / KPAD3, k = idx % KPAD3;
    int r = (k < 256) ? (k + 12) : (k - 256);
    bool valid = (n < TEMPD) && (k < TEMPD);
    float v2 = valid ? W2[(size_t)r * TEMPD + n] : 0.f;
    __nv_bfloat16 h = __float2bfloat16_rn(v2);
    g_wt2h[idx] = h;
    g_wt2l[idx] = __float2bfloat16_rn(v2 - __bfloat162float(h));
    if (n < HID && k < HID) {
        float v1 = W1[(size_t)k * HID + n];
        __nv_bfloat16 h1 = __float2bfloat16_rn(v1);
        g_wt1h[n * HID + k] = h1;
        g_wt1l[n * HID + k] = __float2bfloat16_rn(v1 - __bfloat162float(h1));
    }
    if (k == 0) {
        g_b2p[n] = (n < TEMPD) ? b2[n] : 0.f;
        g_w3p[n] = (n < TEMPD) ? W3[n] : 0.f;
    }
}

// ---------------- HMMA GEMM v5: 128xNTILE CTA, m32x(NTILE/2) warp tile -------
// cp.async 2-stage pipeline, 2 CTAs/SM. NTILE in {128, 64}; n0 = bx*NTILE + noff.
// MODE 1: g_h1[m][n] = lrelu(D + bias[n])
// MODE 2: g_prey[m] += sum_n lrelu(D + g_b2p[n]) * g_w3p[n]
#define SMEM_MMA_BYTES 81920
template <int KCHUNKS, int LDB, int MODE, int NTILE>
__global__ __launch_bounds__(256, 2) void k_mma(const float* __restrict__ bias, int noff)
{
    extern __shared__ __align__(16) __nv_bfloat16 smdyn[];
    const int tid = threadIdx.x;
    const int lane = tid & 31;
    const int wid = tid >> 5;
    const int wm = wid & 3;              // 4 warps over M (32 rows each)
    const int wn = wid >> 2;             // 2 warps over N (NTILE/2 cols each)
    const int m0 = blockIdx.y * 128;
    const int n0 = blockIdx.x * NTILE + noff;
    constexpr int NP = NTILE / 32;       // B 16-row groups per warp
    constexpr int NACC = NTILE / 16;     // accumulator pairs per warp

    const __nv_bfloat16* Bh = (MODE == 1) ? g_wt1h : g_wt2h;
    const __nv_bfloat16* Bl = (MODE == 1) ? g_wt1l : g_wt2l;

    float c[2][NACC][4];
    #pragma unroll
    for (int i = 0; i < 2; i++)
        #pragma unroll
        for (int j = 0; j < NACC; j++)
            #pragma unroll
            for (int q = 0; q < 4; q++) c[i][j][q] = 0.f;

    const int r0s = tid >> 2;
    const int r1s = (tid + 256) >> 2;
    const int c0s = (tid & 3) * 8;
    const int gm0 = m0 + r0s;
    const int gm1 = m0 + r1s;
    const int szA0 = (gm0 < NN) ? 16 : 0;
    const int szA1 = (gm1 < NN) ? 16 : 0;
    const uint32_t smbase = smem_u32(smdyn);

    auto stage_chunk = [&](int kc, int st) {
        const uint32_t sb = smbase + st * 40960;
        const uint32_t off0 = (r0s * 40 + c0s) * 2;
        const uint32_t off1 = (r1s * 40 + c0s) * 2;
        const size_t ga0 = (size_t)gm0 * KPAD3 + kc * 32 + c0s;
        const size_t ga1 = (size_t)gm1 * KPAD3 + kc * 32 + c0s;
        cp16(sb + off0,         g_a3h + ga0, szA0);
        cp16(sb + off1,         g_a3h + ga1, szA1);
        cp16(sb + 10240 + off0, g_a3l + ga0, szA0);
        cp16(sb + 10240 + off1, g_a3l + ga1, szA1);
        const size_t gb0 = (size_t)(n0 + r0s) * LDB + kc * 32 + c0s;
        cp16(sb + 20480 + off0, Bh + gb0, 16);
        cp16(sb + 30720 + off0, Bl + gb0, 16);
        if (NTILE == 128) {
            const size_t gb1 = (size_t)(n0 + r1s) * LDB + kc * 32 + c0s;
            cp16(sb + 20480 + off1, Bh + gb1, 16);
            cp16(sb + 30720 + off1, Bl + gb1, 16);
        }
        CP_COMMIT();
    };

    stage_chunk(0, 0);

    #pragma unroll 1
    for (int kc = 0; kc < KCHUNKS; kc++) {
        const int st = kc & 1;
        CP_WAIT0();
        __syncthreads();
        if (kc + 1 < KCHUNKS) stage_chunk(kc + 1, st ^ 1);

        const uint32_t sb = smbase + st * 40960;
        #pragma unroll
        for (int ks = 0; ks < 2; ks++) {
            const int k0 = ks * 16;
            const int arow = wm * 32 + (lane & 15);
            const int acol = k0 + (lane >> 4) * 8;
            uint32_t ah[2][4], al[2][4];
            ldm_x4(ah[0], sb + (arow * 40 + acol) * 2);
            ldm_x4(ah[1], sb + ((arow + 16) * 40 + acol) * 2);
            ldm_x4(al[0], sb + 10240 + (arow * 40 + acol) * 2);
            ldm_x4(al[1], sb + 10240 + ((arow + 16) * 40 + acol) * 2);

            const int brr = (lane & 7) + ((lane >> 4) << 3);
            const int bcc = k0 + ((lane >> 3) & 1) * 8;
            #pragma unroll
            for (int np = 0; np < NP; np++) {
                const int nb = wn * (NTILE / 2) + np * 16 + brr;
                uint32_t rh[4], rl[4];
                ldm_x4(rh, sb + 20480 + (nb * 40 + bcc) * 2);
                ldm_x4(rl, sb + 30720 + (nb * 40 + bcc) * 2);
                uint32_t bh0[2] = {rh[0], rh[1]}, bh1[2] = {rh[2], rh[3]};
                uint32_t bl0[2] = {rl[0], rl[1]}, bl1[2] = {rl[2], rl[3]};
                #pragma unroll
                for (int mt = 0; mt < 2; mt++) {
                    mma_bf16(c[mt][np * 2],     ah[mt], bh0);
                    mma_bf16(c[mt][np * 2],     ah[mt], bl0);
                    mma_bf16(c[mt][np * 2],     al[mt], bh0);
                    mma_bf16(c[mt][np * 2 + 1], ah[mt], bh1);
                    mma_bf16(c[mt][np * 2 + 1], ah[mt], bl1);
                    mma_bf16(c[mt][np * 2 + 1], al[mt], bh1);
                }
            }
        }
        __syncthreads();
    }

    // ---- epilogue (R10-validated fragment mapping) ----
    const int rbase = m0 + wm * 32 + (lane >> 2);
    const int cbase = wn * (NTILE / 2) + 2 * (lane & 3);
    if (MODE == 1) {
        #pragma unroll
        for (int mt = 0; mt < 2; mt++) {
            const int r0 = rbase + mt * 16;
            const int r1 = r0 + 8;
            #pragma unroll
            for (int nt = 0; nt < NACC; nt++) {
                const int nc = n0 + cbase + nt * 8;
                float b0v = bias[nc], b1v = bias[nc + 1];
                float v0 = c[mt][nt][0] + b0v, v1 = c[mt][nt][1] + b1v;
                float v2 = c[mt][nt][2] + b0v, v3 = c[mt][nt][3] + b1v;
                v0 = (v0 > 0.f) ? v0 : 0.01f * v0;
                v1 = (v1 > 0.f) ? v1 : 0.01f * v1;
                v2 = (v2 > 0.f) ? v2 : 0.01f * v2;
                v3 = (v3 > 0.f) ? v3 : 0.01f * v3;
                if (r0 < NN) *(float2*)&g_h1[(size_t)r0 * HID + nc] = make_float2(v0, v1);
                if (r1 < NN) *(float2*)&g_h1[(size_t)r1 * HID + nc] = make_float2(v2, v3);
            }
        }
    } else {
        #pragma unroll
        for (int mt = 0; mt < 2; mt++) {
            float p0 = 0.f, p1 = 0.f;
            #pragma unroll
            for (int nt = 0; nt < NACC; nt++) {
                const int nc = n0 + cbase + nt * 8;
                float b0v = g_b2p[nc], b1v = g_b2p[nc + 1];
                float w0v = g_w3p[nc], w1v = g_w3p[nc + 1];
                float v0 = c[mt][nt][0] + b0v, v1 = c[mt][nt][1] + b1v;
                float v2 = c[mt][nt][2] + b0v, v3 = c[mt][nt][3] + b1v;
                v0 = (v0 > 0.f) ? v0 : 0.01f * v0;
                v1 = (v1 > 0.f) ? v1 : 0.01f * v1;
                v2 = (v2 > 0.f) ? v2 : 0.01f * v2;
                v3 = (v3 > 0.f) ? v3 : 0.01f * v3;
                p0 += v0 * w0v + v1 * w1v;
                p1 += v2 * w0v + v3 * w1v;
            }
            p0 += __shfl_xor_sync(0xffffffffu, p0, 1);
            p0 += __shfl_xor_sync(0xffffffffu, p0, 2);
            p1 += __shfl_xor_sync(0xffffffffu, p1, 1);
            p1 += __shfl_xor_sync(0xffffffffu, p1, 2);
            if ((lane & 3) == 0) {
                const int r0 = rbase + mt * 16;
                const int r1 = r0 + 8;
                if (r0 < NN) atomicAdd(&g_prey[r0], p0);
                if (r1 < NN) atomicAdd(&g_prey[r1], p1);
            }
        }
    }
}

// ---------------- fused: aggregate x (12-wide) + conv1 in-warp ---------------
__global__ __launch_bounds__(256) void k_aggx1(const float* __restrict__ W0,
                                               const float* __restrict__ b0)
{
    const int lane = threadIdx.x & 31;
    const int node = (blockIdx.x * blockDim.x + threadIdx.x) >> 5;
    if (node >= NN) return;
    const bool act = lane < 3;
    float4 a = make_float4(0.f, 0.f, 0.f, 0.f);
    if (act) {
        a = *(const float4*)&g_x[(size_t)node * TP + lane * 4];
        float sn = g_selfn[node];
        a.x *= sn; a.y *= sn; a.z *= sn; a.w *= sn;
    }
    const int beg = g_rowptr[node];
    const int end = g_rowptr[node + 1];
    for (int base = beg; base < end; base += 32) {
        int idx = base + lane;
        bool ok = idx < end;
        int   s = ok ? g_csrc[idx] : 0;
        float w = ok ? g_cw[idx]   : 0.f;
        int cnt = min(32, end - base);
        int i = 0;
        for (; i + 4 <= cnt; i += 4) {
            int s0 = __shfl_sync(0xffffffffu, s, i);
            int s1 = __shfl_sync(0xffffffffu, s, i + 1);
            int s2 = __shfl_sync(0xffffffffu, s, i + 2);
            int s3 = __shfl_sync(0xffffffffu, s, i + 3);
            float w0 = __shfl_sync(0xffffffffu, w, i);
            float w1 = __shfl_sync(0xffffffffu, w, i + 1);
            float w2 = __shfl_sync(0xffffffffu, w, i + 2);
            float w3 = __shfl_sync(0xffffffffu, w, i + 3);
            if (act) {
                float4 p0 = *(const float4*)&g_x[(size_t)s0 * TP + lane * 4];
                float4 p1 = *(const float4*)&g_x[(size_t)s1 * TP + lane * 4];
                float4 p2 = *(const float4*)&g_x[(size_t)s2 * TP + lane * 4];
                float4 p3 = *(const float4*)&g_x[(size_t)s3 * TP + lane * 4];
                a.x += p0.x * w0 + p1.x * w1 + p2.x * w2 + p3.x * w3;
                a.y += p0.y * w0 + p1.y * w1 + p2.y * w2 + p3.y * w3;
                a.z += p0.z * w0 + p1.z * w1 + p2.z * w2 + p3.z * w3;
                a.w += p0.w * w0 + p1.w * w1 + p2.w * w2 + p3.w * w3;
            }
        }
        for (; i < cnt; i++) {
            int   ss = __shfl_sync(0xffffffffu, s, i);
            float wwv = __shfl_sync(0xffffffffu, w, i);
            if (act) {
                float4 p = *(const float4*)&g_x[(size_t)ss * TP + lane * 4];
                a.x += p.x * wwv; a.y += p.y * wwv;
                a.z += p.z * wwv; a.w += p.w * wwv;
            }
        }
    }
    if (act) {
        uint2 hi, lo;
        split4(a, hi, lo);
        *(uint2*)&g_a3h[(size_t)node * KPAD3 + 256 + lane * 4] = hi;
        *(uint2*)&g_a3l[(size_t)node * KPAD3 + 256 + lane * 4] = lo;
    }
    float axv[TP];
    #pragma unroll
    for (int k2 = 0; k2 < 3; k2++) {
        axv[k2 * 4 + 0] = __shfl_sync(0xffffffffu, a.x, k2);
        axv[k2 * 4 + 1] = __shfl_sync(0xffffffffu, a.y, k2);
        axv[k2 * 4 + 2] = __shfl_sync(0xffffffffu, a.z, k2);
        axv[k2 * 4 + 3] = __shfl_sync(0xffffffffu, a.w, k2);
    }
    float4 h = *(const float4*)&b0[lane * 4];
    #pragma unroll
    for (int k = 0; k < TP; k++) {
        float4 wv = *(const float4*)&W0[k * HID + lane * 4];
        h.x += axv[k] * wv.x; h.y += axv[k] * wv.y;
        h.z += axv[k] * wv.z; h.w += axv[k] * wv.w;
    }
    h.x = (h.x > 0.f) ? h.x : 0.01f * h.x;
    h.y = (h.y > 0.f) ? h.y : 0.01f * h.y;
    h.z = (h.z > 0.f) ? h.z : 0.01f * h.z;
    h.w = (h.w > 0.f) ? h.w : 0.01f * h.w;
    *(float4*)&g_h0[(size_t)node * HID + lane * 4] = h;
}

// ---------------- aggregation of h buffers (128-wide) -----------------------
template <int SRCSEL, int DOFF, int ZEROPREY>
__global__ __launch_bounds__(256) void k_aggu()
{
    const int lane = threadIdx.x & 31;
    const int node = (blockIdx.x * blockDim.x + threadIdx.x) >> 5;
    if (node >= NN) return;
    const float4* src4 = (const float4*)(SRCSEL == 0 ? g_h0 : g_h1);
    float4 acc = src4[(size_t)node * 32 + lane];
    float sn = g_selfn[node];
    acc.x *= sn; acc.y *= sn; acc.z *= sn; acc.w *= sn;
    const int beg = g_rowptr[node];
    const int end = g_rowptr[node + 1];
    for (int base = beg; base < end; base += 32) {
        int idx = base + lane;
        bool ok = idx < end;
        int   s = ok ? g_csrc[idx] : 0;
        float w = ok ? g_cw[idx]   : 0.f;
        int cnt = min(32, end - base);
        int i = 0;
        for (; i + 4 <= cnt; i += 4) {
            int s0 = __shfl_sync(0xffffffffu, s, i);
            int s1 = __shfl_sync(0xffffffffu, s, i + 1);
            int s2 = __shfl_sync(0xffffffffu, s, i + 2);
            int s3 = __shfl_sync(0xffffffffu, s, i + 3);
            float w0 = __shfl_sync(0xffffffffu, w, i);
            float w1 = __shfl_sync(0xffffffffu, w, i + 1);
            float w2 = __shfl_sync(0xffffffffu, w, i + 2);
            float w3 = __shfl_sync(0xffffffffu, w, i + 3);
            float4 p0 = src4[(size_t)s0 * 32 + lane];
            float4 p1 = src4[(size_t)s1 * 32 + lane];
            float4 p2 = src4[(size_t)s2 * 32 + lane];
            float4 p3 = src4[(size_t)s3 * 32 + lane];
            acc.x += p0.x * w0 + p1.x * w1 + p2.x * w2 + p3.x * w3;
            acc.y += p0.y * w0 + p1.y * w1 + p2.y * w2 + p3.y * w3;
            acc.z += p0.z * w0 + p1.z * w1 + p2.z * w2 + p3.z * w3;
            acc.w += p0.w * w0 + p1.w * w1 + p2.w * w2 + p3.w * w3;
        }
        for (; i < cnt; i++) {
            int   ss = __shfl_sync(0xffffffffu, s, i);
            float wwv = __shfl_sync(0xffffffffu, w, i);
            float4 p = src4[(size_t)ss * 32 + lane];
            acc.x += p.x * wwv; acc.y += p.y * wwv;
            acc.z += p.z * wwv; acc.w += p.w * wwv;
        }
    }
    uint2 hi, lo;
    split4(acc, hi, lo);
    *(uint2*)&g_a3h[(size_t)node * KPAD3 + DOFF + lane * 4] = hi;
    *(uint2*)&g_a3l[(size_t)node * KPAD3 + DOFF + lane * 4] = lo;
    if (ZEROPREY && lane == 0) g_prey[node] = 0.f;
}

// ---------------- scalar aggregation + output + autoregressive shift --------
__global__ void k_agg1(const float* __restrict__ b3, float* __restrict__ out, int tstep) {
    int n = blockIdx.x * blockDim.x + threadIdx.x;
    if (n >= NN) return;
    float acc = g_selfn[n] * g_prey[n];
    int beg = g_rowptr[n], end = g_rowptr[n + 1];
    #pragma unroll 4
    for (int i = beg; i < end; i++)
        acc += g_prey[g_csrc[i]] * g_cw[i];
    float yp = acc + b3[0];
    out[(size_t)n * TFUT + tstep] = yp;
    size_t base = (size_t)n * TP;
    float xv[TP - 1];
    #pragma unroll
    for (int j = 0; j < TP - 1; j++) xv[j] = g_x[base + j + 1];
    #pragma unroll
    for (int j = 0; j < TP - 1; j++) g_x[base + j] = xv[j];
    g_x[base + TP - 1] = yp;
}

// ---------------- launch ------------------------------------------------------
extern "C" void kernel_launch(void* const* d_in, const int* in_sizes, int n_in,
                              void* d_out, int out_size)
{
    const float* x  = (const float*)d_in[0];
    const void*  ei = d_in[1];
    const float* ew = (const float*)d_in[2];
    const float* W0 = (const float*)d_in[3];
    const float* b0 = (const float*)d_in[4];
    const float* W1 = (const float*)d_in[5];
    const float* b1 = (const float*)d_in[6];
    const float* W2 = (const float*)d_in[7];
    const float* b2 = (const float*)d_in[8];
    const float* W3 = (const float*)d_in[9];
    const float* b3 = (const float*)d_in[10];
    float* out = (float*)d_out;

    cudaFuncSetAttribute(k_mma<KPAD3 / 32, KPAD3, 2, 128>,
                         cudaFuncAttributeMaxDynamicSharedMemorySize, SMEM_MMA_BYTES);
    cudaFuncSetAttribute(k_mma<KPAD3 / 32, KPAD3, 2, 64>,
                         cudaFuncAttributeMaxDynamicSharedMemorySize, SMEM_MMA_BYTES);
    cudaFuncSetAttribute(k_mma<HID / 32, HID, 1, 128>,
                         cudaFuncAttributeMaxDynamicSharedMemorySize, SMEM_MMA_BYTES);

    const int NB = (NN + 255) / 256;
    const int EB = (EE + 255) / 256;
    const int MT = (NN + 127) / 128;             // 391 row tiles
    const int AGGB = (NN * 32 + 255) / 256;
    const int PWB = (NCPAD3 * KPAD3 + 255) / 256;

    k_init<<<NB, 256>>>(x);
    k_probe<<<EB, 256>>>((const long long*)ei);
    k_cvt<<<EB, 256>>>(ei);
    k_prepw<<<PWB, 256>>>(W1, W2, b2, W3);
    k_deghist<<<EB, 256>>>(ew);
    k_scan<<<1, 1024>>>();
    k_scatter<<<EB, 256>>>(ew);

    for (int t = 0; t < TFUT; t++) {
        k_aggx1<<<AGGB, 256>>>(W0, b0);                              // ax->a3[256:268]; h0
        k_aggu<0, 0, 0><<<AGGB, 256>>>();                            // u0 -> a3[0:128]
        k_mma<HID / 32, HID, 1, 128><<<dim3(1, MT), 256, SMEM_MMA_BYTES>>>(b1, 0); // h1
        k_aggu<1, HID, 1><<<AGGB, 256>>>();                          // u1 -> a3[128:256]; prey=0
        k_mma<KPAD3 / 32, KPAD3, 2, 128><<<dim3(2, MT), 256, SMEM_MMA_BYTES>>>(nullptr, 0);   // cols 0..255
        k_mma<KPAD3 / 32, KPAD3, 2, 64><<<dim3(1, MT), 256, SMEM_MMA_BYTES>>>(nullptr, 256);  // cols 256..319
        k_agg1<<<NB, 256>>>(b3, out, t);                             // yp, out, shift
    }
}

// round 16
// speedup vs baseline: 1.2201x; 1.0198x over previous
#include <cuda_runtime.h>
#include <cuda_bf16.h>
#include <stdint.h>

#define NN 50000
#define EE 800000
#define TP 12
#define HID 128
#define TEMPD 268
#define TFUT 12
#define KPAD3 288          // conv3 K padded: [u0 128 | u1 128 | ax 12 | pad 20]
#define NCPAD3 384         // wt2 allocation width (3rd tile cols 256..383, zero-padded)

// ---------------- scratch ---------------------------------------------------
__device__ int   g_bad;
__device__ int   g_src[EE];
__device__ int   g_dst[EE];
__device__ float g_deg[NN];
__device__ float g_dinv[NN];
__device__ float g_selfn[NN];
__device__ int   g_rowptr[NN + 1];
__device__ int   g_cursor[NN];
__device__ int   g_csrc[EE];
__device__ float g_cw[EE];
__device__ float g_x[(size_t)NN * TP];          // autoregressive window
__device__ float g_h0[(size_t)NN * HID];
__device__ float g_h1[(size_t)NN * HID];
__device__ float g_prey[NN];
// unified bf16 split operand buffer (zero-init -> pad stays zero)
__device__ __nv_bfloat16 g_a3h[(size_t)NN * KPAD3];
__device__ __nv_bfloat16 g_a3l[(size_t)NN * KPAD3];
__device__ __nv_bfloat16 g_wt1h[HID * HID];
__device__ __nv_bfloat16 g_wt1l[HID * HID];
__device__ __nv_bfloat16 g_wt2h[(size_t)NCPAD3 * KPAD3];   // permuted W2^T
__device__ __nv_bfloat16 g_wt2l[(size_t)NCPAD3 * KPAD3];
__device__ float g_b2p[NCPAD3];
__device__ float g_w3p[NCPAD3];

// ---------------- helpers ----------------------------------------------------
__device__ __forceinline__ uint32_t smem_u32(const void* p) {
    uint32_t a;
    asm("{ .reg .u64 t; cvta.to.shared.u64 t, %1; cvt.u32.u64 %0, t; }" : "=r"(a) : "l"(p));
    return a;
}
__device__ __forceinline__ void split4(float4 v, uint2& hi, uint2& lo) {
    __nv_bfloat16 hx = __float2bfloat16_rn(v.x);
    __nv_bfloat16 hy = __float2bfloat16_rn(v.y);
    __nv_bfloat16 hz = __float2bfloat16_rn(v.z);
    __nv_bfloat16 hw = __float2bfloat16_rn(v.w);
    __nv_bfloat16 lx = __float2bfloat16_rn(v.x - __bfloat162float(hx));
    __nv_bfloat16 ly = __float2bfloat16_rn(v.y - __bfloat162float(hy));
    __nv_bfloat16 lz = __float2bfloat16_rn(v.z - __bfloat162float(hz));
    __nv_bfloat16 lw = __float2bfloat16_rn(v.w - __bfloat162float(hw));
    hi.x = (uint32_t)__bfloat16_as_ushort(hx) | ((uint32_t)__bfloat16_as_ushort(hy) << 16);
    hi.y = (uint32_t)__bfloat16_as_ushort(hz) | ((uint32_t)__bfloat16_as_ushort(hw) << 16);
    lo.x = (uint32_t)__bfloat16_as_ushort(lx) | ((uint32_t)__bfloat16_as_ushort(ly) << 16);
    lo.y = (uint32_t)__bfloat16_as_ushort(lz) | ((uint32_t)__bfloat16_as_ushort(lw) << 16);
}
__device__ __forceinline__ void ldm_x4(uint32_t* r, uint32_t addr) {
    asm volatile("ldmatrix.sync.aligned.m8n8.x4.shared.b16 {%0,%1,%2,%3}, [%4];"
                 : "=r"(r[0]), "=r"(r[1]), "=r"(r[2]), "=r"(r[3]) : "r"(addr));
}
__device__ __forceinline__ void mma_bf16(float* c, const uint32_t* a, const uint32_t* b) {
    asm volatile("mma.sync.aligned.m16n8k16.row.col.f32.bf16.bf16.f32 "
                 "{%0,%1,%2,%3}, {%4,%5,%6,%7}, {%8,%9}, {%0,%1,%2,%3};"
                 : "+f"(c[0]), "+f"(c[1]), "+f"(c[2]), "+f"(c[3])
                 : "r"(a[0]), "r"(a[1]), "r"(a[2]), "r"(a[3]), "r"(b[0]), "r"(b[1]));
}
__device__ __forceinline__ void cp16(uint32_t smem, const void* g, int sz) {
    asm volatile("cp.async.cg.shared.global [%0], [%1], 16, %2;"
                 :: "r"(smem), "l"(g), "r"(sz) : "memory");
}
#define CP_COMMIT() asm volatile("cp.async.commit_group;" ::: "memory")
#define CP_WAIT0()  asm volatile("cp.async.wait_group 0;" ::: "memory")

// ---------------- edge-index dtype probe + decode ---------------------------
__global__ void k_probe(const long long* __restrict__ ei) {
    int e = blockIdx.x * blockDim.x + threadIdx.x;
    if (e >= EE) return;
    long long v = ei[e];
    if (v < 0 || v >= NN) atomicOr(&g_bad, 1);
}
__global__ void k_cvt(const void* __restrict__ eiv) {
    int e = blockIdx.x * blockDim.x + threadIdx.x;
    if (e >= EE) return;
    if (g_bad) {
        const int* e32 = (const int*)eiv;
        g_src[e] = e32[e];
        g_dst[e] = e32[EE + e];
    } else {
        const long long* e64 = (const long long*)eiv;
        g_src[e] = (int)e64[e];
        g_dst[e] = (int)e64[EE + e];
    }
}

// ---------------- preprocessing ----------------------------------------------
__global__ void k_init(const float* __restrict__ x) {
    int n = blockIdx.x * blockDim.x + threadIdx.x;
    if (n == 0) g_bad = 0;
    if (n >= NN) return;
    g_deg[n] = 1.0f;
    g_cursor[n] = 0;
    for (int j = 0; j < TP; j++) g_x[n * TP + j] = x[n * TP + j];
}
__global__ void k_deghist(const float* __restrict__ ew) {
    int e = blockIdx.x * blockDim.x + threadIdx.x;
    if (e >= EE) return;
    int d = g_dst[e];
    atomicAdd(&g_deg[d], ew[e]);
    atomicAdd(&g_cursor[d], 1);
}
__global__ void k_scan() {
    __shared__ int sh[1024];
    const int tid = threadIdx.x;
    const int CH = (NN + 1023) / 1024;
    const int start = tid * CH;
    int s = 0;
    for (int i = 0; i < CH; i++) {
        int idx = start + i;
        if (idx < NN) s += g_cursor[idx];
    }
    sh[tid] = s;
    __syncthreads();
    for (int off = 1; off < 1024; off <<= 1) {
        int v = (tid >= off) ? sh[tid - off] : 0;
        __syncthreads();
        sh[tid] += v;
        __syncthreads();
    }
    int run = (tid == 0) ? 0 : sh[tid - 1];
    for (int i = 0; i < CH; i++) {
        int idx = start + i;
        if (idx < NN) {
            int c = g_cursor[idx];
            g_rowptr[idx] = run;
            g_cursor[idx] = run;
            run += c;
            float di = rsqrtf(g_deg[idx]);
            g_dinv[idx] = di;
            g_selfn[idx] = di * di;
        }
    }
    if (tid == 1023) g_rowptr[NN] = sh[1023];
}
__global__ void k_scatter(const float* __restrict__ ew) {
    int e = blockIdx.x * blockDim.x + threadIdx.x;
    if (e >= EE) return;
    int s = g_src[e];
    int d = g_dst[e];
    int pos = atomicAdd(&g_cursor[d], 1);
    g_csrc[pos] = s;
    g_cw[pos] = g_dinv[s] * ew[e] * g_dinv[d];
}

// ---------------- weight prep: transpose + bf16 split + W2 row permutation ---
__global__ void k_prepw(const float* __restrict__ W1, const float* __restrict__ W2,
                        const float* __restrict__ b2, const float* __restrict__ W3) {
    int idx = blockIdx.x * blockDim.x + threadIdx.x;
    if (idx >= NCPAD3 * KPAD3) return;
    int n = idx / KPAD3, k = idx % KPAD3;
    int r = (k < 256) ? (k + 12) : (k - 256);
    bool valid = (n < TEMPD) && (k < TEMPD);
    float v2 = valid ? W2[(size_t)r * TEMPD + n] : 0.f;
    __nv_bfloat16 h = __float2bfloat16_rn(v2);
    g_wt2h[idx] = h;
    g_wt2l[idx] = __float2bfloat16_rn(v2 - __bfloat162float(h));
    if (n < HID && k < HID) {
        float v1 = W1[(size_t)k * HID + n];
        __nv_bfloat16 h1 = __float2bfloat16_rn(v1);
        g_wt1h[n * HID + k] = h1;
        g_wt1l[n * HID + k] = __float2bfloat16_rn(v1 - __bfloat162float(h1));
    }
    if (k == 0) {
        g_b2p[n] = (n < TEMPD) ? b2[n] : 0.f;
        g_w3p[n] = (n < TEMPD) ? W3[n] : 0.f;
    }
}

// ---------------- HMMA GEMM v6: 128x128 CTA, m32n64 warp tile, cp.async -----
// 2-stage pipeline, 2 CTAs/SM. MODE 2 runs grid.x=3: third tile (bx==2,
// cols 256..383) only computes its first 64 columns (the rest are zero weights
// — skipped MMAs leave acc=0 and b2p/w3p pads are 0, so epilogue is exact).
// MODE 1: g_h1[m][n] = lrelu(D + bias[n])
// MODE 2: g_prey[m] += sum_n lrelu(D + g_b2p[n]) * g_w3p[n]
#define SMEM_MMA_BYTES 81920
template <int KCHUNKS, int LDB, int MODE>
__global__ __launch_bounds__(256, 2) void k_mma(const float* __restrict__ bias)
{
    extern __shared__ __align__(16) __nv_bfloat16 smdyn[];
    const int tid = threadIdx.x;
    const int lane = tid & 31;
    const int wid = tid >> 5;
    const int wm = wid & 3;        // 4 warps over M (32 rows each)
    const int wn = wid >> 2;       // 2 warps over N (64 cols each)
    const int m0 = blockIdx.y * 128;
    const int n0 = blockIdx.x * 128;
    // half-tile guard: third conv3 tile computes only np<2 (cols 256..319)
    const int npmax = (MODE == 2 && blockIdx.x == 2) ? 2 : 4;

    const __nv_bfloat16* Bh = (MODE == 1) ? g_wt1h : g_wt2h;
    const __nv_bfloat16* Bl = (MODE == 1) ? g_wt1l : g_wt2l;

    float c[2][8][4];
    #pragma unroll
    for (int i = 0; i < 2; i++)
        #pragma unroll
        for (int j = 0; j < 8; j++)
            #pragma unroll
            for (int q = 0; q < 4; q++) c[i][j][q] = 0.f;

    const int r0s = tid >> 2;
    const int r1s = (tid + 256) >> 2;
    const int c0s = (tid & 3) * 8;
    const int gm0 = m0 + r0s;
    const int gm1 = m0 + r1s;
    const int szA0 = (gm0 < NN) ? 16 : 0;
    const int szA1 = (gm1 < NN) ? 16 : 0;
    const uint32_t smbase = smem_u32(smdyn);

    auto stage_chunk = [&](int kc, int st) {
        const uint32_t sb = smbase + st * 40960;
        const uint32_t off0 = (r0s * 40 + c0s) * 2;
        const uint32_t off1 = (r1s * 40 + c0s) * 2;
        const size_t ga0 = (size_t)gm0 * KPAD3 + kc * 32 + c0s;
        const size_t ga1 = (size_t)gm1 * KPAD3 + kc * 32 + c0s;
        const size_t gb0 = (size_t)(n0 + r0s) * LDB + kc * 32 + c0s;
        const size_t gb1 = (size_t)(n0 + r1s) * LDB + kc * 32 + c0s;
        cp16(sb + off0,         g_a3h + ga0, szA0);
        cp16(sb + off1,         g_a3h + ga1, szA1);
        cp16(sb + 10240 + off0, g_a3l + ga0, szA0);
        cp16(sb + 10240 + off1, g_a3l + ga1, szA1);
        cp16(sb + 20480 + off0, Bh + gb0, 16);
        cp16(sb + 20480 + off1, Bh + gb1, 16);
        cp16(sb + 30720 + off0, Bl + gb0, 16);
        cp16(sb + 30720 + off1, Bl + gb1, 16);
        CP_COMMIT();
    };

    stage_chunk(0, 0);

    #pragma unroll 1
    for (int kc = 0; kc < KCHUNKS; kc++) {
        const int st = kc & 1;
        CP_WAIT0();
        __syncthreads();
        if (kc + 1 < KCHUNKS) stage_chunk(kc + 1, st ^ 1);

        const uint32_t sb = smbase + st * 40960;
        #pragma unroll
        for (int ks = 0; ks < 2; ks++) {
            const int k0 = ks * 16;
            const int arow = wm * 32 + (lane & 15);
            const int acol = k0 + (lane >> 4) * 8;
            uint32_t ah[2][4], al[2][4];
            ldm_x4(ah[0], sb + (arow * 40 + acol) * 2);
            ldm_x4(ah[1], sb + ((arow + 16) * 40 + acol) * 2);
            ldm_x4(al[0], sb + 10240 + (arow * 40 + acol) * 2);
            ldm_x4(al[1], sb + 10240 + ((arow + 16) * 40 + acol) * 2);

            const int brr = (lane & 7) + ((lane >> 4) << 3);
            const int bcc = k0 + ((lane >> 3) & 1) * 8;
            #pragma unroll
            for (int np = 0; np < 4; np++) {
                if (np >= npmax) continue;      // skip zero half of third tile
                const int nb = wn * 64 + np * 16 + brr;
                uint32_t rh[4], rl[4];
                ldm_x4(rh, sb + 20480 + (nb * 40 + bcc) * 2);
                ldm_x4(rl, sb + 30720 + (nb * 40 + bcc) * 2);
                uint32_t bh0[2] = {rh[0], rh[1]}, bh1[2] = {rh[2], rh[3]};
                uint32_t bl0[2] = {rl[0], rl[1]}, bl1[2] = {rl[2], rl[3]};
                #pragma unroll
                for (int mt = 0; mt < 2; mt++) {
                    mma_bf16(c[mt][np * 2],     ah[mt], bh0);
                    mma_bf16(c[mt][np * 2],     ah[mt], bl0);
                    mma_bf16(c[mt][np * 2],     al[mt], bh0);
                    mma_bf16(c[mt][np * 2 + 1], ah[mt], bh1);
                    mma_bf16(c[mt][np * 2 + 1], ah[mt], bl1);
                    mma_bf16(c[mt][np * 2 + 1], al[mt], bh1);
                }
            }
        }
        __syncthreads();
    }

    // ---- epilogue (R10-validated m32n64 mapping) ----
    const int rbase = m0 + wm * 32 + (lane >> 2);
    const int cbase = wn * 64 + 2 * (lane & 3);
    if (MODE == 1) {
        #pragma unroll
        for (int mt = 0; mt < 2; mt++) {
            const int r0 = rbase + mt * 16;
            const int r1 = r0 + 8;
            #pragma unroll
            for (int nt = 0; nt < 8; nt++) {
                const int nc = n0 + cbase + nt * 8;
                float b0v = bias[nc], b1v = bias[nc + 1];
                float v0 = c[mt][nt][0] + b0v, v1 = c[mt][nt][1] + b1v;
                float v2 = c[mt][nt][2] + b0v, v3 = c[mt][nt][3] + b1v;
                v0 = (v0 > 0.f) ? v0 : 0.01f * v0;
                v1 = (v1 > 0.f) ? v1 : 0.01f * v1;
                v2 = (v2 > 0.f) ? v2 : 0.01f * v2;
                v3 = (v3 > 0.f) ? v3 : 0.01f * v3;
                if (r0 < NN) *(float2*)&g_h1[(size_t)r0 * HID + nc] = make_float2(v0, v1);
                if (r1 < NN) *(float2*)&g_h1[(size_t)r1 * HID + nc] = make_float2(v2, v3);
            }
        }
    } else {
        #pragma unroll
        for (int mt = 0; mt < 2; mt++) {
            float p0 = 0.f, p1 = 0.f;
            #pragma unroll
            for (int nt = 0; nt < 8; nt++) {
                const int nc = n0 + cbase + nt * 8;
                float b0v = g_b2p[nc], b1v = g_b2p[nc + 1];
                float w0v = g_w3p[nc], w1v = g_w3p[nc + 1];
                float v0 = c[mt][nt][0] + b0v, v1 = c[mt][nt][1] + b1v;
                float v2 = c[mt][nt][2] + b0v, v3 = c[mt][nt][3] + b1v;
                v0 = (v0 > 0.f) ? v0 : 0.01f * v0;
                v1 = (v1 > 0.f) ? v1 : 0.01f * v1;
                v2 = (v2 > 0.f) ? v2 : 0.01f * v2;
                v3 = (v3 > 0.f) ? v3 : 0.01f * v3;
                p0 += v0 * w0v + v1 * w1v;
                p1 += v2 * w0v + v3 * w1v;
            }
            p0 += __shfl_xor_sync(0xffffffffu, p0, 1);
            p0 += __shfl_xor_sync(0xffffffffu, p0, 2);
            p1 += __shfl_xor_sync(0xffffffffu, p1, 1);
            p1 += __shfl_xor_sync(0xffffffffu, p1, 2);
            if ((lane & 3) == 0) {
                const int r0 = rbase + mt * 16;
                const int r1 = r0 + 8;
                if (r0 < NN) atomicAdd(&g_prey[r0], p0);
                if (r1 < NN) atomicAdd(&g_prey[r1], p1);
            }
        }
    }
}

// ---------------- fused: aggregate x (12-wide) + conv1 in-warp ---------------
__global__ __launch_bounds__(256) void k_aggx1(const float* __restrict__ W0,
                                               const float* __restrict__ b0)
{
    const int lane = threadIdx.x & 31;
    const int node = (blockIdx.x * blockDim.x + threadIdx.x) >> 5;
    if (node >= NN) return;
    const bool act = lane < 3;
    float4 a = make_float4(0.f, 0.f, 0.f, 0.f);
    if (act) {
        a = *(const float4*)&g_x[(size_t)node * TP + lane * 4];
        float sn = g_selfn[node];
        a.x *= sn; a.y *= sn; a.z *= sn; a.w *= sn;
    }
    const int beg = g_rowptr[node];
    const int end = g_rowptr[node + 1];
    for (int base = beg; base < end; base += 32) {
        int idx = base + lane;
        bool ok = idx < end;
        int   s = ok ? g_csrc[idx] : 0;
        float w = ok ? g_cw[idx]   : 0.f;
        int cnt = min(32, end - base);
        int i = 0;
        for (; i + 4 <= cnt; i += 4) {
            int s0 = __shfl_sync(0xffffffffu, s, i);
            int s1 = __shfl_sync(0xffffffffu, s, i + 1);
            int s2 = __shfl_sync(0xffffffffu, s, i + 2);
            int s3 = __shfl_sync(0xffffffffu, s, i + 3);
            float w0 = __shfl_sync(0xffffffffu, w, i);
            float w1 = __shfl_sync(0xffffffffu, w, i + 1);
            float w2 = __shfl_sync(0xffffffffu, w, i + 2);
            float w3 = __shfl_sync(0xffffffffu, w, i + 3);
            if (act) {
                float4 p0 = *(const float4*)&g_x[(size_t)s0 * TP + lane * 4];
                float4 p1 = *(const float4*)&g_x[(size_t)s1 * TP + lane * 4];
                float4 p2 = *(const float4*)&g_x[(size_t)s2 * TP + lane * 4];
                float4 p3 = *(const float4*)&g_x[(size_t)s3 * TP + lane * 4];
                a.x += p0.x * w0 + p1.x * w1 + p2.x * w2 + p3.x * w3;
                a.y += p0.y * w0 + p1.y * w1 + p2.y * w2 + p3.y * w3;
                a.z += p0.z * w0 + p1.z * w1 + p2.z * w2 + p3.z * w3;
                a.w += p0.w * w0 + p1.w * w1 + p2.w * w2 + p3.w * w3;
            }
        }
        for (; i < cnt; i++) {
            int   ss = __shfl_sync(0xffffffffu, s, i);
            float wwv = __shfl_sync(0xffffffffu, w, i);
            if (act) {
                float4 p = *(const float4*)&g_x[(size_t)ss * TP + lane * 4];
                a.x += p.x * wwv; a.y += p.y * wwv;
                a.z += p.z * wwv; a.w += p.w * wwv;
            }
        }
    }
    if (act) {
        uint2 hi, lo;
        split4(a, hi, lo);
        *(uint2*)&g_a3h[(size_t)node * KPAD3 + 256 + lane * 4] = hi;
        *(uint2*)&g_a3l[(size_t)node * KPAD3 + 256 + lane * 4] = lo;
    }
    float axv[TP];
    #pragma unroll
    for (int k2 = 0; k2 < 3; k2++) {
        axv[k2 * 4 + 0] = __shfl_sync(0xffffffffu, a.x, k2);
        axv[k2 * 4 + 1] = __shfl_sync(0xffffffffu, a.y, k2);
        axv[k2 * 4 + 2] = __shfl_sync(0xffffffffu, a.z, k2);
        axv[k2 * 4 + 3] = __shfl_sync(0xffffffffu, a.w, k2);
    }
    float4 h = *(const float4*)&b0[lane * 4];
    #pragma unroll
    for (int k = 0; k < TP; k++) {
        float4 wv = *(const float4*)&W0[k * HID + lane * 4];
        h.x += axv[k] * wv.x; h.y += axv[k] * wv.y;
        h.z += axv[k] * wv.z; h.w += axv[k] * wv.w;
    }
    h.x = (h.x > 0.f) ? h.x : 0.01f * h.x;
    h.y = (h.y > 0.f) ? h.y : 0.01f * h.y;
    h.z = (h.z > 0.f) ? h.z : 0.01f * h.z;
    h.w = (h.w > 0.f) ? h.w : 0.01f * h.w;
    *(float4*)&g_h0[(size_t)node * HID + lane * 4] = h;
}

// ---------------- aggregation of h buffers (128-wide) -----------------------
template <int SRCSEL, int DOFF, int ZEROPREY>
__global__ __launch_bounds__(256) void k_aggu()
{
    const int lane = threadIdx.x & 31;
    const int node = (blockIdx.x * blockDim.x + threadIdx.x) >> 5;
    if (node >= NN) return;
    const float4* src4 = (const float4*)(SRCSEL == 0 ? g_h0 : g_h1);
    float4 acc = src4[(size_t)node * 32 + lane];
    float sn = g_selfn[node];
    acc.x *= sn; acc.y *= sn; acc.z *= sn; acc.w *= sn;
    const int beg = g_rowptr[node];
    const int end = g_rowptr[node + 1];
    for (int base = beg; base < end; base += 32) {
        int idx = base + lane;
        bool ok = idx < end;
        int   s = ok ? g_csrc[idx] : 0;
        float w = ok ? g_cw[idx]   : 0.f;
        int cnt = min(32, end - base);
        int i = 0;
        for (; i + 4 <= cnt; i += 4) {
            int s0 = __shfl_sync(0xffffffffu, s, i);
            int s1 = __shfl_sync(0xffffffffu, s, i + 1);
            int s2 = __shfl_sync(0xffffffffu, s, i + 2);
            int s3 = __shfl_sync(0xffffffffu, s, i + 3);
            float w0 = __shfl_sync(0xffffffffu, w, i);
            float w1 = __shfl_sync(0xffffffffu, w, i + 1);
            float w2 = __shfl_sync(0xffffffffu, w, i + 2);
            float w3 = __shfl_sync(0xffffffffu, w, i + 3);
            float4 p0 = src4[(size_t)s0 * 32 + lane];
            float4 p1 = src4[(size_t)s1 * 32 + lane];
            float4 p2 = src4[(size_t)s2 * 32 + lane];
            float4 p3 = src4[(size_t)s3 * 32 + lane];
            acc.x += p0.x * w0 + p1.x * w1 + p2.x * w2 + p3.x * w3;
            acc.y += p0.y * w0 + p1.y * w1 + p2.y * w2 + p3.y * w3;
            acc.z += p0.z * w0 + p1.z * w1 + p2.z * w2 + p3.z * w3;
            acc.w += p0.w * w0 + p1.w * w1 + p2.w * w2 + p3.w * w3;
        }
        for (; i < cnt; i++) {
            int   ss = __shfl_sync(0xffffffffu, s, i);
            float wwv = __shfl_sync(0xffffffffu, w, i);
            float4 p = src4[(size_t)ss * 32 + lane];
            acc.x += p.x * wwv; acc.y += p.y * wwv;
            acc.z += p.z * wwv; acc.w += p.w * wwv;
        }
    }
    uint2 hi, lo;
    split4(acc, hi, lo);
    *(uint2*)&g_a3h[(size_t)node * KPAD3 + DOFF + lane * 4] = hi;
    *(uint2*)&g_a3l[(size_t)node * KPAD3 + DOFF + lane * 4] = lo;
    if (ZEROPREY && lane == 0) g_prey[node] = 0.f;
}

// ---------------- scalar aggregation + output + autoregressive shift --------
__global__ void k_agg1(const float* __restrict__ b3, float* __restrict__ out, int tstep) {
    int n = blockIdx.x * blockDim.x + threadIdx.x;
    if (n >= NN) return;
    float acc = g_selfn[n] * g_prey[n];
    int beg = g_rowptr[n], end = g_rowptr[n + 1];
    #pragma unroll 4
    for (int i = beg; i < end; i++)
        acc += g_prey[g_csrc[i]] * g_cw[i];
    float yp = acc + b3[0];
    out[(size_t)n * TFUT + tstep] = yp;
    size_t base = (size_t)n * TP;
    float xv[TP - 1];
    #pragma unroll
    for (int j = 0; j < TP - 1; j++) xv[j] = g_x[base + j + 1];
    #pragma unroll
    for (int j = 0; j < TP - 1; j++) g_x[base + j] = xv[j];
    g_x[base + TP - 1] = yp;
}

// ---------------- launch ------------------------------------------------------
extern "C" void kernel_launch(void* const* d_in, const int* in_sizes, int n_in,
                              void* d_out, int out_size)
{
    const float* x  = (const float*)d_in[0];
    const void*  ei = d_in[1];
    const float* ew = (const float*)d_in[2];
    const float* W0 = (const float*)d_in[3];
    const float* b0 = (const float*)d_in[4];
    const float* W1 = (const float*)d_in[5];
    const float* b1 = (const float*)d_in[6];
    const float* W2 = (const float*)d_in[7];
    const float* b2 = (const float*)d_in[8];
    const float* W3 = (const float*)d_in[9];
    const float* b3 = (const float*)d_in[10];
    float* out = (float*)d_out;

    cudaFuncSetAttribute(k_mma<KPAD3 / 32, KPAD3, 2>,
                         cudaFuncAttributeMaxDynamicSharedMemorySize, SMEM_MMA_BYTES);
    cudaFuncSetAttribute(k_mma<HID / 32, HID, 1>,
                         cudaFuncAttributeMaxDynamicSharedMemorySize, SMEM_MMA_BYTES);

    const int NB = (NN + 255) / 256;
    const int EB = (EE + 255) / 256;
    const int MT = (NN + 127) / 128;             // 391 row tiles
    const int AGGB = (NN * 32 + 255) / 256;
    const int PWB = (NCPAD3 * KPAD3 + 255) / 256;

    k_init<<<NB, 256>>>(x);
    k_probe<<<EB, 256>>>((const long long*)ei);
    k_cvt<<<EB, 256>>>(ei);
    k_prepw<<<PWB, 256>>>(W1, W2, b2, W3);
    k_deghist<<<EB, 256>>>(ew);
    k_scan<<<1, 1024>>>();
    k_scatter<<<EB, 256>>>(ew);

    for (int t = 0; t < TFUT; t++) {
        k_aggx1<<<AGGB, 256>>>(W0, b0);                              // ax->a3[256:268]; h0
        k_aggu<0, 0, 0><<<AGGB, 256>>>();                            // u0 -> a3[0:128]
        k_mma<HID / 32, HID, 1><<<dim3(1, MT), 256, SMEM_MMA_BYTES>>>(b1);        // h1
        k_aggu<1, HID, 1><<<AGGB, 256>>>();                          // u1 -> a3[128:256]; prey=0
        k_mma<KPAD3 / 32, KPAD3, 2><<<dim3(3, MT), 256, SMEM_MMA_BYTES>>>(nullptr); // all cols
        k_agg1<<<NB, 256>>>(b3, out, t);                             // yp, out, shift
    }
}

// round 17
// speedup vs baseline: 1.3630x; 1.1171x over previous
#include <cuda_runtime.h>
#include <cuda_bf16.h>
#include <stdint.h>

#define NN 50000
#define EE 800000
#define TP 12
#define HID 128
#define TEMPD 268
#define TFUT 12
#define KPAD3 288          // conv3 K padded: [u0 128 | u1 128 | ax 12 | pad 20]
#define NCPAD3 384         // wt2 allocation width (3rd tile cols 256..383, zero-padded)

// ---------------- scratch ---------------------------------------------------
__device__ int   g_bad;
__device__ int   g_src[EE];
__device__ int   g_dst[EE];
__device__ float g_deg[NN];
__device__ float g_dinv[NN];
__device__ float g_selfn[NN];
__device__ int   g_rowptr[NN + 1];
__device__ int   g_cursor[NN];
__device__ int   g_csrc[EE];
__device__ float g_cw[EE];
__device__ float g_x[(size_t)NN * TP];          // initial window (t=0 only)
__device__ float g_ax[(size_t)NN * TP];         // aggregated window A@x (maintained)
__device__ float g_yp[NN];                      // last step's prediction
__device__ float g_h0[(size_t)NN * HID];
__device__ float g_h1[(size_t)NN * HID];
__device__ float g_prey[NN];
// unified bf16 split operand buffer (zero-init -> pad stays zero)
__device__ __nv_bfloat16 g_a3h[(size_t)NN * KPAD3];
__device__ __nv_bfloat16 g_a3l[(size_t)NN * KPAD3];
__device__ __nv_bfloat16 g_wt1h[HID * HID];
__device__ __nv_bfloat16 g_wt1l[HID * HID];
__device__ __nv_bfloat16 g_wt2h[(size_t)NCPAD3 * KPAD3];   // permuted W2^T
__device__ __nv_bfloat16 g_wt2l[(size_t)NCPAD3 * KPAD3];
__device__ float g_b2p[NCPAD3];
__device__ float g_w3p[NCPAD3];

// ---------------- helpers ----------------------------------------------------
__device__ __forceinline__ uint32_t smem_u32(const void* p) {
    uint32_t a;
    asm("{ .reg .u64 t; cvta.to.shared.u64 t, %1; cvt.u32.u64 %0, t; }" : "=r"(a) : "l"(p));
    return a;
}
__device__ __forceinline__ void split4(float4 v, uint2& hi, uint2& lo) {
    __nv_bfloat16 hx = __float2bfloat16_rn(v.x);
    __nv_bfloat16 hy = __float2bfloat16_rn(v.y);
    __nv_bfloat16 hz = __float2bfloat16_rn(v.z);
    __nv_bfloat16 hw = __float2bfloat16_rn(v.w);
    __nv_bfloat16 lx = __float2bfloat16_rn(v.x - __bfloat162float(hx));
    __nv_bfloat16 ly = __float2bfloat16_rn(v.y - __bfloat162float(hy));
    __nv_bfloat16 lz = __float2bfloat16_rn(v.z - __bfloat162float(hz));
    __nv_bfloat16 lw = __float2bfloat16_rn(v.w - __bfloat162float(hw));
    hi.x = (uint32_t)__bfloat16_as_ushort(hx) | ((uint32_t)__bfloat16_as_ushort(hy) << 16);
    hi.y = (uint32_t)__bfloat16_as_ushort(hz) | ((uint32_t)__bfloat16_as_ushort(hw) << 16);
    lo.x = (uint32_t)__bfloat16_as_ushort(lx) | ((uint32_t)__bfloat16_as_ushort(ly) << 16);
    lo.y = (uint32_t)__bfloat16_as_ushort(lz) | ((uint32_t)__bfloat16_as_ushort(lw) << 16);
}
__device__ __forceinline__ void ldm_x4(uint32_t* r, uint32_t addr) {
    asm volatile("ldmatrix.sync.aligned.m8n8.x4.shared.b16 {%0,%1,%2,%3}, [%4];"
                 : "=r"(r[0]), "=r"(r[1]), "=r"(r[2]), "=r"(r[3]) : "r"(addr));
}
__device__ __forceinline__ void mma_bf16(float* c, const uint32_t* a, const uint32_t* b) {
    asm volatile("mma.sync.aligned.m16n8k16.row.col.f32.bf16.bf16.f32 "
                 "{%0,%1,%2,%3}, {%4,%5,%6,%7}, {%8,%9}, {%0,%1,%2,%3};"
                 : "+f"(c[0]), "+f"(c[1]), "+f"(c[2]), "+f"(c[3])
                 : "r"(a[0]), "r"(a[1]), "r"(a[2]), "r"(a[3]), "r"(b[0]), "r"(b[1]));
}
__device__ __forceinline__ void cp16(uint32_t smem, const void* g, int sz) {
    asm volatile("cp.async.cg.shared.global [%0], [%1], 16, %2;"
                 :: "r"(smem), "l"(g), "r"(sz) : "memory");
}
#define CP_COMMIT() asm volatile("cp.async.commit_group;" ::: "memory")
#define CP_WAIT0()  asm volatile("cp.async.wait_group 0;" ::: "memory")

// ---------------- edge-index dtype probe + decode ---------------------------
__global__ void k_probe(const long long* __restrict__ ei) {
    int e = blockIdx.x * blockDim.x + threadIdx.x;
    if (e >= EE) return;
    long long v = ei[e];
    if (v < 0 || v >= NN) atomicOr(&g_bad, 1);
}
__global__ void k_cvt(const void* __restrict__ eiv) {
    int e = blockIdx.x * blockDim.x + threadIdx.x;
    if (e >= EE) return;
    if (g_bad) {
        const int* e32 = (const int*)eiv;
        g_src[e] = e32[e];
        g_dst[e] = e32[EE + e];
    } else {
        const long long* e64 = (const long long*)eiv;
        g_src[e] = (int)e64[e];
        g_dst[e] = (int)e64[EE + e];
    }
}

// ---------------- preprocessing ----------------------------------------------
__global__ void k_init(const float* __restrict__ x) {
    int n = blockIdx.x * blockDim.x + threadIdx.x;
    if (n == 0) g_bad = 0;
    if (n >= NN) return;
    g_deg[n] = 1.0f;
    g_cursor[n] = 0;
    for (int j = 0; j < TP; j++) g_x[n * TP + j] = x[n * TP + j];
}
__global__ void k_deghist(const float* __restrict__ ew) {
    int e = blockIdx.x * blockDim.x + threadIdx.x;
    if (e >= EE) return;
    int d = g_dst[e];
    atomicAdd(&g_deg[d], ew[e]);
    atomicAdd(&g_cursor[d], 1);
}
__global__ void k_scan() {
    __shared__ int sh[1024];
    const int tid = threadIdx.x;
    const int CH = (NN + 1023) / 1024;
    const int start = tid * CH;
    int s = 0;
    for (int i = 0; i < CH; i++) {
        int idx = start + i;
        if (idx < NN) s += g_cursor[idx];
    }
    sh[tid] = s;
    __syncthreads();
    for (int off = 1; off < 1024; off <<= 1) {
        int v = (tid >= off) ? sh[tid - off] : 0;
        __syncthreads();
        sh[tid] += v;
        __syncthreads();
    }
    int run = (tid == 0) ? 0 : sh[tid - 1];
    for (int i = 0; i < CH; i++) {
        int idx = start + i;
        if (idx < NN) {
            int c = g_cursor[idx];
            g_rowptr[idx] = run;
            g_cursor[idx] = run;
            run += c;
            float di = rsqrtf(g_deg[idx]);
            g_dinv[idx] = di;
            g_selfn[idx] = di * di;
        }
    }
    if (tid == 1023) g_rowptr[NN] = sh[1023];
}
__global__ void k_scatter(const float* __restrict__ ew) {
    int e = blockIdx.x * blockDim.x + threadIdx.x;
    if (e >= EE) return;
    int s = g_src[e];
    int d = g_dst[e];
    int pos = atomicAdd(&g_cursor[d], 1);
    g_csrc[pos] = s;
    g_cw[pos] = g_dinv[s] * ew[e] * g_dinv[d];
}

// ---------------- weight prep: transpose + bf16 split + W2 row permutation ---
__global__ void k_prepw(const float* __restrict__ W1, const float* __restrict__ W2,
                        const float* __restrict__ b2, const float* __restrict__ W3) {
    int idx = blockIdx.x * blockDim.x + threadIdx.x;
    if (idx >= NCPAD3 * KPAD3) return;
    int n = idx / KPAD3, k = idx % KPAD3;
    int r = (k < 256) ? (k + 12) : (k - 256);
    bool valid = (n < TEMPD) && (k < TEMPD);
    float v2 = valid ? W2[(size_t)r * TEMPD + n] : 0.f;
    __nv_bfloat16 h = __float2bfloat16_rn(v2);
    g_wt2h[idx] = h;
    g_wt2l[idx] = __float2bfloat16_rn(v2 - __bfloat162float(h));
    if (n < HID && k < HID) {
        float v1 = W1[(size_t)k * HID + n];
        __nv_bfloat16 h1 = __float2bfloat16_rn(v1);
        g_wt1h[n * HID + k] = h1;
        g_wt1l[n * HID + k] = __float2bfloat16_rn(v1 - __bfloat162float(h1));
    }
    if (k == 0) {
        g_b2p[n] = (n < TEMPD) ? b2[n] : 0.f;
        g_w3p[n] = (n < TEMPD) ? W3[n] : 0.f;
    }
}

// ---------------- HMMA GEMM: 128x128 CTA, m32n64 warp tile, cp.async --------
// MODE 2 grid.x=3: third tile computes only first 64 cols (rest are zero pads).
#define SMEM_MMA_BYTES 81920
template <int KCHUNKS, int LDB, int MODE>
__global__ __launch_bounds__(256, 2) void k_mma(const float* __restrict__ bias)
{
    extern __shared__ __align__(16) __nv_bfloat16 smdyn[];
    const int tid = threadIdx.x;
    const int lane = tid & 31;
    const int wid = tid >> 5;
    const int wm = wid & 3;
    const int wn = wid >> 2;
    const int m0 = blockIdx.y * 128;
    const int n0 = blockIdx.x * 128;
    const int npmax = (MODE == 2 && blockIdx.x == 2) ? 2 : 4;

    const __nv_bfloat16* Bh = (MODE == 1) ? g_wt1h : g_wt2h;
    const __nv_bfloat16* Bl = (MODE == 1) ? g_wt1l : g_wt2l;

    float c[2][8][4];
    #pragma unroll
    for (int i = 0; i < 2; i++)
        #pragma unroll
        for (int j = 0; j < 8; j++)
            #pragma unroll
            for (int q = 0; q < 4; q++) c[i][j][q] = 0.f;

    const int r0s = tid >> 2;
    const int r1s = (tid + 256) >> 2;
    const int c0s = (tid & 3) * 8;
    const int gm0 = m0 + r0s;
    const int gm1 = m0 + r1s;
    const int szA0 = (gm0 < NN) ? 16 : 0;
    const int szA1 = (gm1 < NN) ? 16 : 0;
    const uint32_t smbase = smem_u32(smdyn);

    auto stage_chunk = [&](int kc, int st) {
        const uint32_t sb = smbase + st * 40960;
        const uint32_t off0 = (r0s * 40 + c0s) * 2;
        const uint32_t off1 = (r1s * 40 + c0s) * 2;
        const size_t ga0 = (size_t)gm0 * KPAD3 + kc * 32 + c0s;
        const size_t ga1 = (size_t)gm1 * KPAD3 + kc * 32 + c0s;
        const size_t gb0 = (size_t)(n0 + r0s) * LDB + kc * 32 + c0s;
        const size_t gb1 = (size_t)(n0 + r1s) * LDB + kc * 32 + c0s;
        cp16(sb + off0,         g_a3h + ga0, szA0);
        cp16(sb + off1,         g_a3h + ga1, szA1);
        cp16(sb + 10240 + off0, g_a3l + ga0, szA0);
        cp16(sb + 10240 + off1, g_a3l + ga1, szA1);
        cp16(sb + 20480 + off0, Bh + gb0, 16);
        cp16(sb + 20480 + off1, Bh + gb1, 16);
        cp16(sb + 30720 + off0, Bl + gb0, 16);
        cp16(sb + 30720 + off1, Bl + gb1, 16);
        CP_COMMIT();
    };

    stage_chunk(0, 0);

    #pragma unroll 1
    for (int kc = 0; kc < KCHUNKS; kc++) {
        const int st = kc & 1;
        CP_WAIT0();
        __syncthreads();
        if (kc + 1 < KCHUNKS) stage_chunk(kc + 1, st ^ 1);

        const uint32_t sb = smbase + st * 40960;
        #pragma unroll
        for (int ks = 0; ks < 2; ks++) {
            const int k0 = ks * 16;
            const int arow = wm * 32 + (lane & 15);
            const int acol = k0 + (lane >> 4) * 8;
            uint32_t ah[2][4], al[2][4];
            ldm_x4(ah[0], sb + (arow * 40 + acol) * 2);
            ldm_x4(ah[1], sb + ((arow + 16) * 40 + acol) * 2);
            ldm_x4(al[0], sb + 10240 + (arow * 40 + acol) * 2);
            ldm_x4(al[1], sb + 10240 + ((arow + 16) * 40 + acol) * 2);

            const int brr = (lane & 7) + ((lane >> 4) << 3);
            const int bcc = k0 + ((lane >> 3) & 1) * 8;
            #pragma unroll
            for (int np = 0; np < 4; np++) {
                if (np >= npmax) continue;
                const int nb = wn * 64 + np * 16 + brr;
                uint32_t rh[4], rl[4];
                ldm_x4(rh, sb + 20480 + (nb * 40 + bcc) * 2);
                ldm_x4(rl, sb + 30720 + (nb * 40 + bcc) * 2);
                uint32_t bh0[2] = {rh[0], rh[1]}, bh1[2] = {rh[2], rh[3]};
                uint32_t bl0[2] = {rl[0], rl[1]}, bl1[2] = {rl[2], rl[3]};
                #pragma unroll
                for (int mt = 0; mt < 2; mt++) {
                    mma_bf16(c[mt][np * 2],     ah[mt], bh0);
                    mma_bf16(c[mt][np * 2],     ah[mt], bl0);
                    mma_bf16(c[mt][np * 2],     al[mt], bh0);
                    mma_bf16(c[mt][np * 2 + 1], ah[mt], bh1);
                    mma_bf16(c[mt][np * 2 + 1], ah[mt], bl1);
                    mma_bf16(c[mt][np * 2 + 1], al[mt], bh1);
                }
            }
        }
        __syncthreads();
    }

    const int rbase = m0 + wm * 32 + (lane >> 2);
    const int cbase = wn * 64 + 2 * (lane & 3);
    if (MODE == 1) {
        #pragma unroll
        for (int mt = 0; mt < 2; mt++) {
            const int r0 = rbase + mt * 16;
            const int r1 = r0 + 8;
            #pragma unroll
            for (int nt = 0; nt < 8; nt++) {
                const int nc = n0 + cbase + nt * 8;
                float b0v = bias[nc], b1v = bias[nc + 1];
                float v0 = c[mt][nt][0] + b0v, v1 = c[mt][nt][1] + b1v;
                float v2 = c[mt][nt][2] + b0v, v3 = c[mt][nt][3] + b1v;
                v0 = (v0 > 0.f) ? v0 : 0.01f * v0;
                v1 = (v1 > 0.f) ? v1 : 0.01f * v1;
                v2 = (v2 > 0.f) ? v2 : 0.01f * v2;
                v3 = (v3 > 0.f) ? v3 : 0.01f * v3;
                if (r0 < NN) *(float2*)&g_h1[(size_t)r0 * HID + nc] = make_float2(v0, v1);
                if (r1 < NN) *(float2*)&g_h1[(size_t)r1 * HID + nc] = make_float2(v2, v3);
            }
        }
    } else {
        #pragma unroll
        for (int mt = 0; mt < 2; mt++) {
            float p0 = 0.f, p1 = 0.f;
            #pragma unroll
            for (int nt = 0; nt < 8; nt++) {
                const int nc = n0 + cbase + nt * 8;
                float b0v = g_b2p[nc], b1v = g_b2p[nc + 1];
                float w0v = g_w3p[nc], w1v = g_w3p[nc + 1];
                float v0 = c[mt][nt][0] + b0v, v1 = c[mt][nt][1] + b1v;
                float v2 = c[mt][nt][2] + b0v, v3 = c[mt][nt][3] + b1v;
                v0 = (v0 > 0.f) ? v0 : 0.01f * v0;
                v1 = (v1 > 0.f) ? v1 : 0.01f * v1;
                v2 = (v2 > 0.f) ? v2 : 0.01f * v2;
                v3 = (v3 > 0.f) ? v3 : 0.01f * v3;
                p0 += v0 * w0v + v1 * w1v;
                p1 += v2 * w0v + v3 * w1v;
            }
            p0 += __shfl_xor_sync(0xffffffffu, p0, 1);
            p0 += __shfl_xor_sync(0xffffffffu, p0, 2);
            p1 += __shfl_xor_sync(0xffffffffu, p1, 1);
            p1 += __shfl_xor_sync(0xffffffffu, p1, 2);
            if ((lane & 3) == 0) {
                const int r0 = rbase + mt * 16;
                const int r1 = r0 + 8;
                if (r0 < NN) atomicAdd(&g_prey[r0], p0);
                if (r1 < NN) atomicAdd(&g_prey[r1], p1);
            }
        }
    }
}

// ---------------- shared tail: h0 compute + ax/a3 stores (warp-level) -------
__device__ __forceinline__ void finish_ax(const float* __restrict__ W0,
                                          const float* __restrict__ b0,
                                          int node, int lane, const float* axv)
{
    const bool act = lane < 3;
    if (act) {
        float4 av = make_float4(axv[lane * 4], axv[lane * 4 + 1],
                                axv[lane * 4 + 2], axv[lane * 4 + 3]);
        *(float4*)&g_ax[(size_t)node * TP + lane * 4] = av;
        uint2 hi, lo;
        split4(av, hi, lo);
        *(uint2*)&g_a3h[(size_t)node * KPAD3 + 256 + lane * 4] = hi;
        *(uint2*)&g_a3l[(size_t)node * KPAD3 + 256 + lane * 4] = lo;
    }
    float4 h = *(const float4*)&b0[lane * 4];
    #pragma unroll
    for (int k = 0; k < TP; k++) {
        float4 wv = *(const float4*)&W0[k * HID + lane * 4];
        h.x += axv[k] * wv.x; h.y += axv[k] * wv.y;
        h.z += axv[k] * wv.z; h.w += axv[k] * wv.w;
    }
    h.x = (h.x > 0.f) ? h.x : 0.01f * h.x;
    h.y = (h.y > 0.f) ? h.y : 0.01f * h.y;
    h.z = (h.z > 0.f) ? h.z : 0.01f * h.z;
    h.w = (h.w > 0.f) ? h.w : 0.01f * h.w;
    *(float4*)&g_h0[(size_t)node * HID + lane * 4] = h;
}

// ---------------- t=0: full 12-wide x gather + conv1 ------------------------
__global__ __launch_bounds__(256) void k_aggx1(const float* __restrict__ W0,
                                               const float* __restrict__ b0)
{
    const int lane = threadIdx.x & 31;
    const int node = (blockIdx.x * blockDim.x + threadIdx.x) >> 5;
    if (node >= NN) return;
    const bool act = lane < 3;
    float4 a = make_float4(0.f, 0.f, 0.f, 0.f);
    if (act) {
        a = *(const float4*)&g_x[(size_t)node * TP + lane * 4];
        float sn = g_selfn[node];
        a.x *= sn; a.y *= sn; a.z *= sn; a.w *= sn;
    }
    const int beg = g_rowptr[node];
    const int end = g_rowptr[node + 1];
    for (int base = beg; base < end; base += 32) {
        int idx = base + lane;
        bool ok = idx < end;
        int   s = ok ? g_csrc[idx] : 0;
        float w = ok ? g_cw[idx]   : 0.f;
        int cnt = min(32, end - base);
        int i = 0;
        for (; i + 4 <= cnt; i += 4) {
            int s0 = __shfl_sync(0xffffffffu, s, i);
            int s1 = __shfl_sync(0xffffffffu, s, i + 1);
            int s2 = __shfl_sync(0xffffffffu, s, i + 2);
            int s3 = __shfl_sync(0xffffffffu, s, i + 3);
            float w0 = __shfl_sync(0xffffffffu, w, i);
            float w1 = __shfl_sync(0xffffffffu, w, i + 1);
            float w2 = __shfl_sync(0xffffffffu, w, i + 2);
            float w3 = __shfl_sync(0xffffffffu, w, i + 3);
            if (act) {
                float4 p0 = *(const float4*)&g_x[(size_t)s0 * TP + lane * 4];
                float4 p1 = *(const float4*)&g_x[(size_t)s1 * TP + lane * 4];
                float4 p2 = *(const float4*)&g_x[(size_t)s2 * TP + lane * 4];
                float4 p3 = *(const float4*)&g_x[(size_t)s3 * TP + lane * 4];
                a.x += p0.x * w0 + p1.x * w1 + p2.x * w2 + p3.x * w3;
                a.y += p0.y * w0 + p1.y * w1 + p2.y * w2 + p3.y * w3;
                a.z += p0.z * w0 + p1.z * w1 + p2.z * w2 + p3.z * w3;
                a.w += p0.w * w0 + p1.w * w1 + p2.w * w2 + p3.w * w3;
            }
        }
        for (; i < cnt; i++) {
            int   ss = __shfl_sync(0xffffffffu, s, i);
            float wwv = __shfl_sync(0xffffffffu, w, i);
            if (act) {
                float4 p = *(const float4*)&g_x[(size_t)ss * TP + lane * 4];
                a.x += p.x * wwv; a.y += p.y * wwv;
                a.z += p.z * wwv; a.w += p.w * wwv;
            }
        }
    }
    float axv[TP];
    #pragma unroll
    for (int k2 = 0; k2 < 3; k2++) {
        axv[k2 * 4 + 0] = __shfl_sync(0xffffffffu, a.x, k2);
        axv[k2 * 4 + 1] = __shfl_sync(0xffffffffu, a.y, k2);
        axv[k2 * 4 + 2] = __shfl_sync(0xffffffffu, a.z, k2);
        axv[k2 * 4 + 3] = __shfl_sync(0xffffffffu, a.w, k2);
    }
    finish_ax(W0, b0, node, lane, axv);
}

// ---------------- t>=1: shift ax + scalar gather of yp + conv1 --------------
// ax_new[0:11] = ax_old[1:12]; ax_new[11] = A·yp (scalar gather, all lanes)
__global__ __launch_bounds__(256) void k_axup(const float* __restrict__ W0,
                                              const float* __restrict__ b0)
{
    const int lane = threadIdx.x & 31;
    const int node = (blockIdx.x * blockDim.x + threadIdx.x) >> 5;
    if (node >= NN) return;
    const int beg = g_rowptr[node];
    const int end = g_rowptr[node + 1];
    float acc = 0.f;
    for (int i = beg + lane; i < end; i += 32)
        acc += g_yp[g_csrc[i]] * g_cw[i];
    #pragma unroll
    for (int off = 16; off > 0; off >>= 1)
        acc += __shfl_xor_sync(0xffffffffu, acc, off);
    const float ayp = acc + g_selfn[node] * g_yp[node];

    float4 a_old = make_float4(0.f, 0.f, 0.f, 0.f);
    if (lane < 3)
        a_old = *(const float4*)&g_ax[(size_t)node * TP + lane * 4];
    float axo[TP];
    #pragma unroll
    for (int k2 = 0; k2 < 3; k2++) {
        axo[k2 * 4 + 0] = __shfl_sync(0xffffffffu, a_old.x, k2);
        axo[k2 * 4 + 1] = __shfl_sync(0xffffffffu, a_old.y, k2);
        axo[k2 * 4 + 2] = __shfl_sync(0xffffffffu, a_old.z, k2);
        axo[k2 * 4 + 3] = __shfl_sync(0xffffffffu, a_old.w, k2);
    }
    float axv[TP];
    #pragma unroll
    for (int j = 0; j < TP - 1; j++) axv[j] = axo[j + 1];
    axv[TP - 1] = ayp;
    finish_ax(W0, b0, node, lane, axv);
}

// ---------------- aggregation of h buffers (128-wide) -----------------------
template <int SRCSEL, int DOFF, int ZEROPREY>
__global__ __launch_bounds__(256) void k_aggu()
{
    const int lane = threadIdx.x & 31;
    const int node = (blockIdx.x * blockDim.x + threadIdx.x) >> 5;
    if (node >= NN) return;
    const float4* src4 = (const float4*)(SRCSEL == 0 ? g_h0 : g_h1);
    float4 acc = src4[(size_t)node * 32 + lane];
    float sn = g_selfn[node];
    acc.x *= sn; acc.y *= sn; acc.z *= sn; acc.w *= sn;
    const int beg = g_rowptr[node];
    const int end = g_rowptr[node + 1];
    for (int base = beg; base < end; base += 32) {
        int idx = base + lane;
        bool ok = idx < end;
        int   s = ok ? g_csrc[idx] : 0;
        float w = ok ? g_cw[idx]   : 0.f;
        int cnt = min(32, end - base);
        int i = 0;
        for (; i + 4 <= cnt; i += 4) {
            int s0 = __shfl_sync(0xffffffffu, s, i);
            int s1 = __shfl_sync(0xffffffffu, s, i + 1);
            int s2 = __shfl_sync(0xffffffffu, s, i + 2);
            int s3 = __shfl_sync(0xffffffffu, s, i + 3);
            float w0 = __shfl_sync(0xffffffffu, w, i);
            float w1 = __shfl_sync(0xffffffffu, w, i + 1);
            float w2 = __shfl_sync(0xffffffffu, w, i + 2);
            float w3 = __shfl_sync(0xffffffffu, w, i + 3);
            float4 p0 = src4[(size_t)s0 * 32 + lane];
            float4 p1 = src4[(size_t)s1 * 32 + lane];
            float4 p2 = src4[(size_t)s2 * 32 + lane];
            float4 p3 = src4[(size_t)s3 * 32 + lane];
            acc.x += p0.x * w0 + p1.x * w1 + p2.x * w2 + p3.x * w3;
            acc.y += p0.y * w0 + p1.y * w1 + p2.y * w2 + p3.y * w3;
            acc.z += p0.z * w0 + p1.z * w1 + p2.z * w2 + p3.z * w3;
            acc.w += p0.w * w0 + p1.w * w1 + p2.w * w2 + p3.w * w3;
        }
        for (; i < cnt; i++) {
            int   ss = __shfl_sync(0xffffffffu, s, i);
            float wwv = __shfl_sync(0xffffffffu, w, i);
            float4 p = src4[(size_t)ss * 32 + lane];
            acc.x += p.x * wwv; acc.y += p.y * wwv;
            acc.z += p.z * wwv; acc.w += p.w * wwv;
        }
    }
    uint2 hi, lo;
    split4(acc, hi, lo);
    *(uint2*)&g_a3h[(size_t)node * KPAD3 + DOFF + lane * 4] = hi;
    *(uint2*)&g_a3l[(size_t)node * KPAD3 + DOFF + lane * 4] = lo;
    if (ZEROPREY && lane == 0) g_prey[node] = 0.f;
}

// ---------------- scalar aggregation + output ------------------------------
__global__ void k_agg1(const float* __restrict__ b3, float* __restrict__ out, int tstep) {
    int n = blockIdx.x * blockDim.x + threadIdx.x;
    if (n >= NN) return;
    float acc = g_selfn[n] * g_prey[n];
    int beg = g_rowptr[n], end = g_rowptr[n + 1];
    #pragma unroll 4
    for (int i = beg; i < end; i++)
        acc += g_prey[g_csrc[i]] * g_cw[i];
    float yp = acc + b3[0];
    out[(size_t)n * TFUT + tstep] = yp;
    g_yp[n] = yp;
}

// ---------------- launch ------------------------------------------------------
extern "C" void kernel_launch(void* const* d_in, const int* in_sizes, int n_in,
                              void* d_out, int out_size)
{
    const float* x  = (const float*)d_in[0];
    const void*  ei = d_in[1];
    const float* ew = (const float*)d_in[2];
    const float* W0 = (const float*)d_in[3];
    const float* b0 = (const float*)d_in[4];
    const float* W1 = (const float*)d_in[5];
    const float* b1 = (const float*)d_in[6];
    const float* W2 = (const float*)d_in[7];
    const float* b2 = (const float*)d_in[8];
    const float* W3 = (const float*)d_in[9];
    const float* b3 = (const float*)d_in[10];
    float* out = (float*)d_out;

    cudaFuncSetAttribute(k_mma<KPAD3 / 32, KPAD3, 2>,
                         cudaFuncAttributeMaxDynamicSharedMemorySize, SMEM_MMA_BYTES);
    cudaFuncSetAttribute(k_mma<HID / 32, HID, 1>,
                         cudaFuncAttributeMaxDynamicSharedMemorySize, SMEM_MMA_BYTES);

    const int NB = (NN + 255) / 256;
    const int EB = (EE + 255) / 256;
    const int MT = (NN + 127) / 128;             // 391 row tiles
    const int AGGB = (NN * 32 + 255) / 256;
    const int PWB = (NCPAD3 * KPAD3 + 255) / 256;

    k_init<<<NB, 256>>>(x);
    k_probe<<<EB, 256>>>((const long long*)ei);
    k_cvt<<<EB, 256>>>(ei);
    k_prepw<<<PWB, 256>>>(W1, W2, b2, W3);
    k_deghist<<<EB, 256>>>(ew);
    k_scan<<<1, 1024>>>();
    k_scatter<<<EB, 256>>>(ew);

    for (int t = 0; t < TFUT; t++) {
        if (t == 0) k_aggx1<<<AGGB, 256>>>(W0, b0);                  // full x gather
        else        k_axup<<<AGGB, 256>>>(W0, b0);                   // shift + scalar gather
        k_aggu<0, 0, 0><<<AGGB, 256>>>();                            // u0 -> a3[0:128]
        k_mma<HID / 32, HID, 1><<<dim3(1, MT), 256, SMEM_MMA_BYTES>>>(b1);        // h1
        k_aggu<1, HID, 1><<<AGGB, 256>>>();                          // u1 -> a3[128:256]; prey=0
        k_mma<KPAD3 / 32, KPAD3, 2><<<dim3(3, MT), 256, SMEM_MMA_BYTES>>>(nullptr); // conv3
        k_agg1<<<NB, 256>>>(b3, out, t);                             // yp, out
    }
}